// round 8
// baseline (speedup 1.0000x reference)
#include <cuda_runtime.h>
#include <math.h>

#define B_   2
#define S_   2048
#define D_   1024
#define H_   16
#define HD_  64
#define MTOT (B_ * S_)        // 4096

// Scratch (__device__ globals; no cudaMalloc allowed)
__device__ float g_qkv[MTOT * 3 * D_];   // ~50 MB
__device__ float g_att[MTOT * D_];       // ~17 MB

// ---------------------------------------------------------------------------
// SGEMM: C[M,N] = A[M,K] @ W[K,N] + bias[N]
// 128x128 tile, BK=8, 256 threads, 8x8/thread, DOUBLE-BUFFERED smem with
// register prefetch. One __syncthreads per k-step; LDG overlaps compute.
// ---------------------------------------------------------------------------
__global__ __launch_bounds__(256, 2)
void sgemm128(const float* __restrict__ A, const float* __restrict__ W,
              const float* __restrict__ bias, float* __restrict__ C,
              int M, int N, int K) {
    __shared__ float As[2][8][128];   // [buf][k][m]
    __shared__ float Bs[2][8][128];   // [buf][k][n]

    const int tid = threadIdx.x;
    const int tx  = tid & 15;      // n
    const int ty  = tid >> 4;      // m
    const int m0  = blockIdx.y * 128;
    const int n0  = blockIdx.x * 128;

    const int arow = tid >> 1;           // 0..127
    const int ac4  = (tid & 1) * 4;      // 0 or 4
    const int brow = tid >> 5;           // 0..7
    const int bc4  = (tid & 31) * 4;     // 0..124

    float acc[2][2][4][4] = {};

    const float* aptr = A + (size_t)(m0 + arow) * K + ac4;
    const float* bptr = W + (size_t)brow * N + n0 + bc4;

    // preload tile 0 into buf 0
    {
        float4 av = *(const float4*)(aptr);
        As[0][ac4 + 0][arow] = av.x;
        As[0][ac4 + 1][arow] = av.y;
        As[0][ac4 + 2][arow] = av.z;
        As[0][ac4 + 3][arow] = av.w;
        *(float4*)&Bs[0][brow][bc4] = *(const float4*)(bptr);
    }
    __syncthreads();

    int buf = 0;
    for (int k0 = 8; k0 <= K; k0 += 8) {
        float4 an, bn;
        const bool more = (k0 < K);
        if (more) {
            an = *(const float4*)(aptr + k0);
            bn = *(const float4*)(bptr + (size_t)k0 * N);
        }

#pragma unroll
        for (int kk = 0; kk < 8; kk++) {
            float4 a0 = *(const float4*)&As[buf][kk][ty * 4];
            float4 a1 = *(const float4*)&As[buf][kk][ty * 4 + 64];
            float4 b0 = *(const float4*)&Bs[buf][kk][tx * 4];
            float4 b1 = *(const float4*)&Bs[buf][kk][tx * 4 + 64];
            float ar[2][4] = {{a0.x, a0.y, a0.z, a0.w}, {a1.x, a1.y, a1.z, a1.w}};
            float br[2][4] = {{b0.x, b0.y, b0.z, b0.w}, {b1.x, b1.y, b1.z, b1.w}};
#pragma unroll
            for (int ai = 0; ai < 2; ai++)
#pragma unroll
                for (int bi = 0; bi < 2; bi++)
#pragma unroll
                    for (int i = 0; i < 4; i++)
#pragma unroll
                        for (int j = 0; j < 4; j++)
                            acc[ai][bi][i][j] += ar[ai][i] * br[bi][j];
        }

        if (more) {
            const int nb = buf ^ 1;
            As[nb][ac4 + 0][arow] = an.x;
            As[nb][ac4 + 1][arow] = an.y;
            As[nb][ac4 + 2][arow] = an.z;
            As[nb][ac4 + 3][arow] = an.w;
            *(float4*)&Bs[nb][brow][bc4] = bn;
            __syncthreads();
            buf = nb;
        }
    }

    float4 bb[2];
    bb[0] = *(const float4*)(bias + n0 + tx * 4);
    bb[1] = *(const float4*)(bias + n0 + tx * 4 + 64);
#pragma unroll
    for (int ai = 0; ai < 2; ai++)
#pragma unroll
        for (int i = 0; i < 4; i++) {
            int m = m0 + ty * 4 + i + ai * 64;
            float* crow = C + (size_t)m * N + n0;
#pragma unroll
            for (int bi = 0; bi < 2; bi++) {
                float4 v;
                v.x = acc[ai][bi][i][0] + ((const float*)&bb[bi])[0];
                v.y = acc[ai][bi][i][1] + ((const float*)&bb[bi])[1];
                v.z = acc[ai][bi][i][2] + ((const float*)&bb[bi])[2];
                v.w = acc[ai][bi][i][3] + ((const float*)&bb[bi])[3];
                *(float4*)(crow + tx * 4 + bi * 64) = v;
            }
        }
}

// ---------------------------------------------------------------------------
// Flash attention, 64q x 128k score tile, 256 threads, 4x8/thread.
// smem = Qt[64][64] + Kt[64][128] + Vs[128][64] (XOR-swizzled) + Ps[64][128]
//      = 112 KB  -> 2 CTAs/SM (16 warps) for latency hiding.
// P rows are produced and consumed by the same 16-thread ty-group (one
// half-warp), so only __syncwarp() is needed between softmax and PV.
// ---------------------------------------------------------------------------
__global__ __launch_bounds__(256, 2)
void attention_kernel(const float* __restrict__ qkv, float* __restrict__ out) {
    extern __shared__ float sm[];
    float* Qt = sm;                    // [64 d][64 q]
    float* Kt = Qt + 64 * 64;          // [64 d][128 k]
    float* Vs = Kt + 64 * 128;         // [128 k][64 d] swizzled granules
    float* Ps = Vs + 128 * 64;         // [64 q][128 k]

    const int tid = threadIdx.x;
    const int tx  = tid & 15;
    const int ty  = tid >> 4;
    const int bh  = blockIdx.x;
    const int b   = bh >> 4;
    const int h   = bh & 15;
    const int q0  = blockIdx.y * 64;

    const float* base = qkv + (size_t)b * S_ * (3 * D_);
    const int qoff = h * HD_;
    const int koff = D_ + h * HD_;
    const int voff = 2 * D_ + h * HD_;

    // Q loader: row qr = tid>>2 (0..63), cols qc..qc+15
    {
        const int qr = tid >> 2;
        const int qc = (tid & 3) * 16;
        const float* qp = base + (size_t)(q0 + qr) * (3 * D_) + qoff + qc;
#pragma unroll
        for (int i = 0; i < 4; i++) {
            float4 v = *(const float4*)(qp + i * 4);
            Qt[(qc + i * 4 + 0) * 64 + qr] = v.x;
            Qt[(qc + i * 4 + 1) * 64 + qr] = v.y;
            Qt[(qc + i * 4 + 2) * 64 + qr] = v.z;
            Qt[(qc + i * 4 + 3) * 64 + qr] = v.w;
        }
    }

    float m_i[4], l_i[4], o[4][4];
#pragma unroll
    for (int i = 0; i < 4; i++) {
        m_i[i] = -1e30f;
        l_i[i] = 0.f;
#pragma unroll
        for (int j = 0; j < 4; j++) o[i][j] = 0.f;
    }

    const float scale = 0.125f;   // 1/sqrt(64)

    // K/V loader mapping: row lr = tid>>1 (0..127), col half lc = (tid&1)*32
    const int lr  = tid >> 1;
    const int lc  = (tid & 1) * 32;
    const int lg0 = lc >> 2;            // granule base 0 or 8
    const int vsw = lr & 7;             // V granule swizzle

    for (int kt = 0; kt < S_ / 128; kt++) {
        const int k0 = kt * 128;
        {
            const float* rowp = base + (size_t)(k0 + lr) * (3 * D_);
            const float* kp = rowp + koff + lc;
            const float* vp = rowp + voff + lc;
#pragma unroll
            for (int i = 0; i < 8; i++) {
                float4 kv = *(const float4*)(kp + i * 4);
                Kt[(lc + i * 4 + 0) * 128 + lr] = kv.x;
                Kt[(lc + i * 4 + 1) * 128 + lr] = kv.y;
                Kt[(lc + i * 4 + 2) * 128 + lr] = kv.z;
                Kt[(lc + i * 4 + 3) * 128 + lr] = kv.w;
                // V: logical granule (lg0+i) stored at physical (lg0+i)^vsw
                *(float4*)&Vs[lr * 64 + (((lg0 + i) ^ vsw) << 2)] =
                    *(const float4*)(vp + i * 4);
            }
        }
        __syncthreads();

        // scores s[ki][i][j]: q rows ty*4+i, k cols tx*4+j+64*ki
        float s[2][4][4] = {};
#pragma unroll 8
        for (int dd = 0; dd < 64; dd++) {
            float4 a0 = *(const float4*)&Qt[dd * 64 + ty * 4];
            float4 b0 = *(const float4*)&Kt[dd * 128 + tx * 4];
            float4 b1 = *(const float4*)&Kt[dd * 128 + tx * 4 + 64];
            float ar[4] = {a0.x, a0.y, a0.z, a0.w};
            float br[2][4] = {{b0.x, b0.y, b0.z, b0.w}, {b1.x, b1.y, b1.z, b1.w}};
#pragma unroll
            for (int ki = 0; ki < 2; ki++)
#pragma unroll
                for (int i = 0; i < 4; i++)
#pragma unroll
                    for (int j = 0; j < 4; j++)
                        s[ki][i][j] += ar[i] * br[ki][j];
        }

        // online softmax per q-row (16 tx lanes of a half-warp share a row)
#pragma unroll
        for (int i = 0; i < 4; i++) {
            const int row = ty * 4 + i;
            float mx = -1e30f;
#pragma unroll
            for (int ki = 0; ki < 2; ki++)
#pragma unroll
                for (int j = 0; j < 4; j++) {
                    s[ki][i][j] *= scale;
                    mx = fmaxf(mx, s[ki][i][j]);
                }
#pragma unroll
            for (int off = 8; off >= 1; off >>= 1)
                mx = fmaxf(mx, __shfl_xor_sync(0xffffffffu, mx, off));
            float m_new = fmaxf(m_i[i], mx);
            float alpha = __expf(m_i[i] - m_new);
            float rs = 0.f;
#pragma unroll
            for (int ki = 0; ki < 2; ki++) {
                float4 pv;
                pv.x = __expf(s[ki][i][0] - m_new);
                pv.y = __expf(s[ki][i][1] - m_new);
                pv.z = __expf(s[ki][i][2] - m_new);
                pv.w = __expf(s[ki][i][3] - m_new);
                rs += pv.x + pv.y + pv.z + pv.w;
                *(float4*)&Ps[row * 128 + tx * 4 + ki * 64] = pv;
            }
#pragma unroll
            for (int off = 8; off >= 1; off >>= 1)
                rs += __shfl_xor_sync(0xffffffffu, rs, off);
            l_i[i] = l_i[i] * alpha + rs;
            m_i[i] = m_new;
#pragma unroll
            for (int j = 0; j < 4; j++) o[i][j] *= alpha;
        }
        __syncwarp();   // P producers == P consumers (same half-warp)

        // O += P @ V : o[i][j], d cols tx*4+j
#pragma unroll 4
        for (int kk4 = 0; kk4 < 32; kk4++) {
            float4 vf[4];
#pragma unroll
            for (int t = 0; t < 4; t++) {
                const int kk = kk4 * 4 + t;
                vf[t] = *(const float4*)&Vs[kk * 64 + ((tx ^ (kk & 7)) << 2)];
            }
#pragma unroll
            for (int i = 0; i < 4; i++) {
                float4 pf = *(const float4*)&Ps[(ty * 4 + i) * 128 + kk4 * 4];
#pragma unroll
                for (int j = 0; j < 4; j++) {
                    o[i][j] += pf.x * ((const float*)&vf[0])[j]
                             + pf.y * ((const float*)&vf[1])[j]
                             + pf.z * ((const float*)&vf[2])[j]
                             + pf.w * ((const float*)&vf[3])[j];
                }
            }
        }
        __syncthreads();
    }

    // write out[b, q, h*64 + d]
#pragma unroll
    for (int i = 0; i < 4; i++) {
        const int q = q0 + ty * 4 + i;
        const float inv = 1.f / l_i[i];
        float4 v;
        v.x = o[i][0] * inv;
        v.y = o[i][1] * inv;
        v.z = o[i][2] * inv;
        v.w = o[i][3] * inv;
        *(float4*)(out + ((size_t)(b * S_ + q)) * D_ + h * HD_ + tx * 4) = v;
    }
}

// ---------------------------------------------------------------------------
extern "C" void kernel_launch(void* const* d_in, const int* in_sizes, int n_in,
                              void* d_out, int out_size) {
    const float* x     = (const float*)d_in[0];
    const float* Wqkv  = (const float*)d_in[1];
    const float* bqkv  = (const float*)d_in[2];
    const float* Wproj = (const float*)d_in[3];
    const float* bproj = (const float*)d_in[4];
    float* out = (float*)d_out;

    float *qkv, *att;
    cudaGetSymbolAddress((void**)&qkv, g_qkv);
    cudaGetSymbolAddress((void**)&att, g_att);

    const int attn_smem = (64 * 64 + 64 * 128 + 128 * 64 + 64 * 128) * (int)sizeof(float); // 114688
    cudaFuncSetAttribute(attention_kernel,
                         cudaFuncAttributeMaxDynamicSharedMemorySize, attn_smem);

    // 1) QKV projection: [4096,1024] @ [1024,3072]
    sgemm128<<<dim3(3 * D_ / 128, MTOT / 128), 256>>>(x, Wqkv, bqkv, qkv,
                                                      MTOT, 3 * D_, D_);
    // 2) attention
    attention_kernel<<<dim3(B_ * H_, S_ / 64), 256, attn_smem>>>(qkv, att);

    // 3) output projection: [4096,1024] @ [1024,1024]
    sgemm128<<<dim3(D_ / 128, MTOT / 128), 256>>>(att, Wproj, bproj, out,
                                                  MTOT, D_, D_);
}

// round 9
// speedup vs baseline: 1.0749x; 1.0749x over previous
#include <cuda_runtime.h>
#include <math.h>

#define B_   2
#define S_   2048
#define D_   1024
#define H_   16
#define HD_  64
#define MTOT (B_ * S_)        // 4096

// Scratch (__device__ globals; no cudaMalloc allowed)
__device__ float g_qkv[MTOT * 3 * D_];   // ~50 MB
__device__ float g_att[MTOT * D_];       // ~17 MB

// ---------------------------------------------------------------------------
// SGEMM (unchanged R8 winner): 128x128, BK=8, 256 thr, 8x8/thr,
// double-buffered smem + register prefetch, one sync per k-step.
// ---------------------------------------------------------------------------
__global__ __launch_bounds__(256, 2)
void sgemm128(const float* __restrict__ A, const float* __restrict__ W,
              const float* __restrict__ bias, float* __restrict__ C,
              int M, int N, int K) {
    __shared__ float As[2][8][128];
    __shared__ float Bs[2][8][128];

    const int tid = threadIdx.x;
    const int tx  = tid & 15;
    const int ty  = tid >> 4;
    const int m0  = blockIdx.y * 128;
    const int n0  = blockIdx.x * 128;

    const int arow = tid >> 1;
    const int ac4  = (tid & 1) * 4;
    const int brow = tid >> 5;
    const int bc4  = (tid & 31) * 4;

    float acc[2][2][4][4] = {};

    const float* aptr = A + (size_t)(m0 + arow) * K + ac4;
    const float* bptr = W + (size_t)brow * N + n0 + bc4;

    {
        float4 av = *(const float4*)(aptr);
        As[0][ac4 + 0][arow] = av.x;
        As[0][ac4 + 1][arow] = av.y;
        As[0][ac4 + 2][arow] = av.z;
        As[0][ac4 + 3][arow] = av.w;
        *(float4*)&Bs[0][brow][bc4] = *(const float4*)(bptr);
    }
    __syncthreads();

    int buf = 0;
    for (int k0 = 8; k0 <= K; k0 += 8) {
        float4 an, bn;
        const bool more = (k0 < K);
        if (more) {
            an = *(const float4*)(aptr + k0);
            bn = *(const float4*)(bptr + (size_t)k0 * N);
        }

#pragma unroll
        for (int kk = 0; kk < 8; kk++) {
            float4 a0 = *(const float4*)&As[buf][kk][ty * 4];
            float4 a1 = *(const float4*)&As[buf][kk][ty * 4 + 64];
            float4 b0 = *(const float4*)&Bs[buf][kk][tx * 4];
            float4 b1 = *(const float4*)&Bs[buf][kk][tx * 4 + 64];
            float ar[2][4] = {{a0.x, a0.y, a0.z, a0.w}, {a1.x, a1.y, a1.z, a1.w}};
            float br[2][4] = {{b0.x, b0.y, b0.z, b0.w}, {b1.x, b1.y, b1.z, b1.w}};
#pragma unroll
            for (int ai = 0; ai < 2; ai++)
#pragma unroll
                for (int bi = 0; bi < 2; bi++)
#pragma unroll
                    for (int i = 0; i < 4; i++)
#pragma unroll
                        for (int j = 0; j < 4; j++)
                            acc[ai][bi][i][j] += ar[ai][i] * br[bi][j];
        }

        if (more) {
            const int nb = buf ^ 1;
            As[nb][ac4 + 0][arow] = an.x;
            As[nb][ac4 + 1][arow] = an.y;
            As[nb][ac4 + 2][arow] = an.z;
            As[nb][ac4 + 3][arow] = an.w;
            *(float4*)&Bs[nb][brow][bc4] = bn;
            __syncthreads();
            buf = nb;
        }
    }

    float4 bb[2];
    bb[0] = *(const float4*)(bias + n0 + tx * 4);
    bb[1] = *(const float4*)(bias + n0 + tx * 4 + 64);
#pragma unroll
    for (int ai = 0; ai < 2; ai++)
#pragma unroll
        for (int i = 0; i < 4; i++) {
            int m = m0 + ty * 4 + i + ai * 64;
            float* crow = C + (size_t)m * N + n0;
#pragma unroll
            for (int bi = 0; bi < 2; bi++) {
                float4 v;
                v.x = acc[ai][bi][i][0] + ((const float*)&bb[bi])[0];
                v.y = acc[ai][bi][i][1] + ((const float*)&bb[bi])[1];
                v.z = acc[ai][bi][i][2] + ((const float*)&bb[bi])[2];
                v.w = acc[ai][bi][i][3] + ((const float*)&bb[bi])[3];
                *(float4*)(crow + tx * 4 + bi * 64) = v;
            }
        }
}

// ---------------------------------------------------------------------------
// Flash attention: 128q x 128k tile, 512 threads (16 warps, ONE CTA/SM),
// 4q x 8k per thread. Double-buffered K/V with register prefetch; one
// __syncthreads per k-tile. P rows produced+consumed by same half-warp.
// smem: Qt[64][128] + Kt[2][64][128] + Vs[2][128][64] + Ps[128][128]
//     = 57344 floats = 224 KB.
// ---------------------------------------------------------------------------
#define ATTN_SMEM_FLOATS (64 * 128 + 2 * 64 * 128 + 2 * 128 * 64 + 128 * 128)

__global__ __launch_bounds__(512, 1)
void attention_kernel(const float* __restrict__ qkv, float* __restrict__ out) {
    extern __shared__ float sm[];
    float* Qt  = sm;                       // [64 d][128 q]
    float* Kt0 = Qt + 64 * 128;            // [64 d][128 k] buf 0
    float* Kt1 = Kt0 + 64 * 128;           // buf 1
    float* Vs0 = Kt1 + 64 * 128;           // [128 k][64 d] swizzled, buf 0
    float* Vs1 = Vs0 + 128 * 64;           // buf 1
    float* Ps  = Vs1 + 128 * 64;           // [128 q][128 k]

    const int tid = threadIdx.x;
    const int tx  = tid & 15;              // k group (8 cols: tx*4+j, +64)
    const int ty  = tid >> 4;              // q group (rows ty*4+i), 0..31
    const int bh  = blockIdx.x;
    const int b   = bh >> 4;
    const int h   = bh & 15;
    const int q0  = blockIdx.y * 128;

    const float* base = qkv + (size_t)b * S_ * (3 * D_);
    const int qoff = h * HD_;
    const int koff = D_ + h * HD_;
    const int voff = 2 * D_ + h * HD_;

    // loader mapping (Q, K, V identical): row lr = tid>>2 (0..127),
    // d-chunk lc = (tid&3)*16 (4 float4)
    const int lr = tid >> 2;
    const int lc = (tid & 3) * 16;
    const int g0 = lc >> 2;                // V granule base (0,4,8,12)
    const int vsw = lr & 7;

    // ---- load Q (transposed) + first K/V tile into buf 0 ----
    {
        const float* qp = base + (size_t)(q0 + lr) * (3 * D_) + qoff + lc;
        const float* kp = base + (size_t)lr * (3 * D_) + koff + lc;
        const float* vp = base + (size_t)lr * (3 * D_) + voff + lc;
#pragma unroll
        for (int i = 0; i < 4; i++) {
            float4 qv = *(const float4*)(qp + i * 4);
            Qt[(lc + i * 4 + 0) * 128 + lr] = qv.x;
            Qt[(lc + i * 4 + 1) * 128 + lr] = qv.y;
            Qt[(lc + i * 4 + 2) * 128 + lr] = qv.z;
            Qt[(lc + i * 4 + 3) * 128 + lr] = qv.w;
            float4 kv = *(const float4*)(kp + i * 4);
            Kt0[(lc + i * 4 + 0) * 128 + lr] = kv.x;
            Kt0[(lc + i * 4 + 1) * 128 + lr] = kv.y;
            Kt0[(lc + i * 4 + 2) * 128 + lr] = kv.z;
            Kt0[(lc + i * 4 + 3) * 128 + lr] = kv.w;
            *(float4*)&Vs0[lr * 64 + (((g0 + i) ^ vsw) << 2)] =
                *(const float4*)(vp + i * 4);
        }
    }
    __syncthreads();

    float m_i[4], l_i[4], o[4][4];
#pragma unroll
    for (int i = 0; i < 4; i++) {
        m_i[i] = -1e30f;
        l_i[i] = 0.f;
#pragma unroll
        for (int j = 0; j < 4; j++) o[i][j] = 0.f;
    }

    const float scale = 0.125f;   // 1/sqrt(64)
    int buf = 0;

    for (int kt = 0; kt < S_ / 128; kt++) {
        // ---- prefetch next K/V tile into registers ----
        float4 kr[4], vr[4];
        const bool more = (kt + 1 < S_ / 128);
        if (more) {
            const float* rowp = base + (size_t)((kt + 1) * 128 + lr) * (3 * D_);
            const float* kp = rowp + koff + lc;
            const float* vp = rowp + voff + lc;
#pragma unroll
            for (int i = 0; i < 4; i++) {
                kr[i] = *(const float4*)(kp + i * 4);
                vr[i] = *(const float4*)(vp + i * 4);
            }
        }

        const float* Kt = buf ? Kt1 : Kt0;
        const float* Vs = buf ? Vs1 : Vs0;

        // ---- QK^T: s[ki][i][j], q rows ty*4+i, k cols tx*4+j+64*ki ----
        float s[2][4][4] = {};
#pragma unroll 8
        for (int dd = 0; dd < 64; dd++) {
            float4 a0 = *(const float4*)&Qt[dd * 128 + ty * 4];
            float4 b0 = *(const float4*)&Kt[dd * 128 + tx * 4];
            float4 b1 = *(const float4*)&Kt[dd * 128 + tx * 4 + 64];
            float ar[4] = {a0.x, a0.y, a0.z, a0.w};
            float br[2][4] = {{b0.x, b0.y, b0.z, b0.w}, {b1.x, b1.y, b1.z, b1.w}};
#pragma unroll
            for (int ki = 0; ki < 2; ki++)
#pragma unroll
                for (int i = 0; i < 4; i++)
#pragma unroll
                    for (int j = 0; j < 4; j++)
                        s[ki][i][j] += ar[i] * br[ki][j];
        }

        // ---- online softmax per q-row (16 tx lanes share a row) ----
#pragma unroll
        for (int i = 0; i < 4; i++) {
            const int row = ty * 4 + i;
            float mx = -1e30f;
#pragma unroll
            for (int ki = 0; ki < 2; ki++)
#pragma unroll
                for (int j = 0; j < 4; j++) {
                    s[ki][i][j] *= scale;
                    mx = fmaxf(mx, s[ki][i][j]);
                }
#pragma unroll
            for (int off = 8; off >= 1; off >>= 1)
                mx = fmaxf(mx, __shfl_xor_sync(0xffffffffu, mx, off));
            float m_new = fmaxf(m_i[i], mx);
            float alpha = __expf(m_i[i] - m_new);
            float rs = 0.f;
#pragma unroll
            for (int ki = 0; ki < 2; ki++) {
                float4 pv;
                pv.x = __expf(s[ki][i][0] - m_new);
                pv.y = __expf(s[ki][i][1] - m_new);
                pv.z = __expf(s[ki][i][2] - m_new);
                pv.w = __expf(s[ki][i][3] - m_new);
                rs += pv.x + pv.y + pv.z + pv.w;
                *(float4*)&Ps[row * 128 + tx * 4 + ki * 64] = pv;
            }
#pragma unroll
            for (int off = 8; off >= 1; off >>= 1)
                rs += __shfl_xor_sync(0xffffffffu, rs, off);
            l_i[i] = l_i[i] * alpha + rs;
            m_i[i] = m_new;
#pragma unroll
            for (int j = 0; j < 4; j++) o[i][j] *= alpha;
        }
        __syncwarp();   // P producers == consumers (same half-warp)

        // ---- O += P @ V : d cols tx*4+j ----
#pragma unroll 4
        for (int kk4 = 0; kk4 < 32; kk4++) {
            float4 vf[4];
#pragma unroll
            for (int t = 0; t < 4; t++) {
                const int kk = kk4 * 4 + t;
                vf[t] = *(const float4*)&Vs[kk * 64 + ((tx ^ (kk & 7)) << 2)];
            }
#pragma unroll
            for (int i = 0; i < 4; i++) {
                float4 pf = *(const float4*)&Ps[(ty * 4 + i) * 128 + kk4 * 4];
#pragma unroll
                for (int j = 0; j < 4; j++) {
                    o[i][j] += pf.x * ((const float*)&vf[0])[j]
                             + pf.y * ((const float*)&vf[1])[j]
                             + pf.z * ((const float*)&vf[2])[j]
                             + pf.w * ((const float*)&vf[3])[j];
                }
            }
        }

        // ---- store prefetched tile into the other buffer ----
        if (more) {
            float* Ktn = buf ? Kt0 : Kt1;
            float* Vsn = buf ? Vs0 : Vs1;
#pragma unroll
            for (int i = 0; i < 4; i++) {
                Ktn[(lc + i * 4 + 0) * 128 + lr] = kr[i].x;
                Ktn[(lc + i * 4 + 1) * 128 + lr] = kr[i].y;
                Ktn[(lc + i * 4 + 2) * 128 + lr] = kr[i].z;
                Ktn[(lc + i * 4 + 3) * 128 + lr] = kr[i].w;
                *(float4*)&Vsn[lr * 64 + (((g0 + i) ^ vsw) << 2)] = vr[i];
            }
        }
        __syncthreads();
        buf ^= 1;
    }

    // ---- write out[b, q, h*64 + d] ----
#pragma unroll
    for (int i = 0; i < 4; i++) {
        const int q = q0 + ty * 4 + i;
        const float inv = 1.f / l_i[i];
        float4 v;
        v.x = o[i][0] * inv;
        v.y = o[i][1] * inv;
        v.z = o[i][2] * inv;
        v.w = o[i][3] * inv;
        *(float4*)(out + ((size_t)(b * S_ + q)) * D_ + h * HD_ + tx * 4) = v;
    }
}

// ---------------------------------------------------------------------------
extern "C" void kernel_launch(void* const* d_in, const int* in_sizes, int n_in,
                              void* d_out, int out_size) {
    const float* x     = (const float*)d_in[0];
    const float* Wqkv  = (const float*)d_in[1];
    const float* bqkv  = (const float*)d_in[2];
    const float* Wproj = (const float*)d_in[3];
    const float* bproj = (const float*)d_in[4];
    float* out = (float*)d_out;

    float *qkv, *att;
    cudaGetSymbolAddress((void**)&qkv, g_qkv);
    cudaGetSymbolAddress((void**)&att, g_att);

    const int attn_smem = ATTN_SMEM_FLOATS * (int)sizeof(float);  // 229376
    cudaFuncSetAttribute(attention_kernel,
                         cudaFuncAttributeMaxDynamicSharedMemorySize, attn_smem);

    // 1) QKV projection: [4096,1024] @ [1024,3072]
    sgemm128<<<dim3(3 * D_ / 128, MTOT / 128), 256>>>(x, Wqkv, bqkv, qkv,
                                                      MTOT, 3 * D_, D_);
    // 2) attention
    attention_kernel<<<dim3(B_ * H_, S_ / 128), 512, attn_smem>>>(qkv, att);

    // 3) output projection: [4096,1024] @ [1024,1024]
    sgemm128<<<dim3(D_ / 128, MTOT / 128), 256>>>(att, Wproj, bproj, out,
                                                  MTOT, D_, D_);
}

// round 10
// speedup vs baseline: 1.3311x; 1.2384x over previous
#include <cuda_runtime.h>
#include <cuda_bf16.h>
#include <cstdint>
#include <math.h>

#define B_   2
#define S_   2048
#define D_   1024
#define H_   16
#define HD_  64
#define MTOT (B_ * S_)        // 4096

// Scratch (__device__ globals; no cudaMalloc allowed)
__device__ float g_qkv[MTOT * 3 * D_];            // 50 MB
__device__ float g_att[MTOT * D_];                // 17 MB
__device__ __nv_bfloat16 g_ahi[MTOT * D_];        // 8 MB
__device__ __nv_bfloat16 g_alo[MTOT * D_];        // 8 MB
__device__ __nv_bfloat16 g_bthi[3 * D_ * D_];     // 6 MB  (W^T, [N][K])
__device__ __nv_bfloat16 g_btlo[3 * D_ * D_];     // 6 MB

// ---------------------------------------------------------------------------
// helpers
// ---------------------------------------------------------------------------
__device__ __forceinline__ uint32_t smem_u32(const void* p) {
    uint32_t a;
    asm("{ .reg .u64 t; cvta.to.shared.u64 t, %1; cvt.u32.u64 %0, t; }"
        : "=r"(a) : "l"(p));
    return a;
}

#define LDSM4(r0, r1, r2, r3, addr) \
    asm volatile("ldmatrix.sync.aligned.m8n8.x4.shared.b16 {%0,%1,%2,%3}, [%4];" \
                 : "=r"(r0), "=r"(r1), "=r"(r2), "=r"(r3) : "r"(addr))
#define LDSM2(r0, r1, addr) \
    asm volatile("ldmatrix.sync.aligned.m8n8.x2.shared.b16 {%0,%1}, [%2];" \
                 : "=r"(r0), "=r"(r1) : "r"(addr))

#define MMA_BF16(c, a, b) \
    asm volatile("mma.sync.aligned.m16n8k16.row.col.f32.bf16.bf16.f32 " \
                 "{%0,%1,%2,%3}, {%4,%5,%6,%7}, {%8,%9}, {%0,%1,%2,%3};" \
                 : "+f"((c)[0]), "+f"((c)[1]), "+f"((c)[2]), "+f"((c)[3]) \
                 : "r"((a)[0]), "r"((a)[1]), "r"((a)[2]), "r"((a)[3]), \
                   "r"((b)[0]), "r"((b)[1]))

__device__ __forceinline__ uint32_t pack_bf16(float a, float b) {
    __nv_bfloat162 t = __floats2bfloat162_rn(a, b);
    return *reinterpret_cast<uint32_t*>(&t);
}

// ---------------------------------------------------------------------------
// Prep: split fp32 -> bf16 hi/lo  (rowwise, [M][K] layout preserved)
// ---------------------------------------------------------------------------
__global__ void split_bf16(const float* __restrict__ src,
                           __nv_bfloat16* __restrict__ hi,
                           __nv_bfloat16* __restrict__ lo, int n4) {
    int i = blockIdx.x * blockDim.x + threadIdx.x;
    if (i >= n4) return;
    float4 v = ((const float4*)src)[i];
    float h0 = __bfloat162float(__float2bfloat16_rn(v.x));
    float h1 = __bfloat162float(__float2bfloat16_rn(v.y));
    float h2 = __bfloat162float(__float2bfloat16_rn(v.z));
    float h3 = __bfloat162float(__float2bfloat16_rn(v.w));
    uint2 ho, lw;
    ho.x = pack_bf16(h0, h1);
    ho.y = pack_bf16(h2, h3);
    lw.x = pack_bf16(v.x - h0, v.y - h1);
    lw.y = pack_bf16(v.z - h2, v.w - h3);
    ((uint2*)hi)[i] = ho;
    ((uint2*)lo)[i] = lw;
}

// Prep: W[K][N] fp32 -> W^T hi/lo bf16 [N][K]
__global__ void transpose_split_bf16(const float* __restrict__ W,
                                     __nv_bfloat16* __restrict__ Thi,
                                     __nv_bfloat16* __restrict__ Tlo,
                                     int K, int N) {
    __shared__ float t[32][33];
    int n0 = blockIdx.x * 32, k0 = blockIdx.y * 32;
    int tx = threadIdx.x, ty = threadIdx.y;   // 32 x 8
#pragma unroll
    for (int i = 0; i < 4; i++)
        t[ty + 8 * i][tx] = W[(size_t)(k0 + ty + 8 * i) * N + n0 + tx];
    __syncthreads();
#pragma unroll
    for (int i = 0; i < 4; i++) {
        float v = t[tx][ty + 8 * i];
        float h = __bfloat162float(__float2bfloat16_rn(v));
        size_t o = (size_t)(n0 + ty + 8 * i) * K + k0 + tx;
        Thi[o] = __float2bfloat16_rn(h);
        Tlo[o] = __float2bfloat16_rn(v - h);
    }
}

// ---------------------------------------------------------------------------
// Tensor-core GEMM: C[M,N] = A @ W + bias, 3-term bf16 split.
// A as Ahi/Alo [M][K] bf16; W^T as Bhi/Blo [N][K] bf16.
// 128x128 tile, BK=32, 256 thr (8 warps, 2m x 4n), warp tile 64x32.
// Double-buffered smem (4 mats x 128 x BKP bf16), one sync per k-step.
// ---------------------------------------------------------------------------
#define BKP 40                      // padded k extent (bf16) -> 80 B rows
#define MATB (128 * BKP * 2)        // 10240 B per matrix
#define BUFB (4 * MATB)             // 40960 B per buffer
#define GEMM_SMEM (2 * BUFB)        // 81920 B

__global__ __launch_bounds__(256, 1)
void gemm_bf16x3(const __nv_bfloat16* __restrict__ Ahi,
                 const __nv_bfloat16* __restrict__ Alo,
                 const __nv_bfloat16* __restrict__ Bhi,
                 const __nv_bfloat16* __restrict__ Blo,
                 const float* __restrict__ bias, float* __restrict__ C,
                 int M, int N, int K) {
    extern __shared__ char smraw[];
    const int tid  = threadIdx.x;
    const int lane = tid & 31;
    const int wid  = tid >> 5;
    const int m0   = blockIdx.y * 128;
    const int n0   = blockIdx.x * 128;
    const int m0w  = (wid >> 2) * 64;   // warp m offset in tile
    const int n0w  = (wid & 3) * 32;    // warp n offset in tile
    const uint32_t sb = smem_u32(smraw);

    // loaders: row = tid>>1 (0..127), 16 bf16 at k-offset (tid&1)*16
    const int lrow = tid >> 1;
    const int lk   = (tid & 1) * 16;
    const __nv_bfloat16* gAh = Ahi + (size_t)(m0 + lrow) * K + lk;
    const __nv_bfloat16* gAl = Alo + (size_t)(m0 + lrow) * K + lk;
    const __nv_bfloat16* gBh = Bhi + (size_t)(n0 + lrow) * K + lk;
    const __nv_bfloat16* gBl = Blo + (size_t)(n0 + lrow) * K + lk;
    const uint32_t sdst = (uint32_t)(lrow * (BKP * 2) + lk * 2);

    float c[4][4][4] = {};

    // ldmatrix per-lane address components (byte offsets inside a matrix)
    const int arow = lane & 15;            // A: rows of the two 8-row halves
    const int acol = (lane >> 4) * 8;      // A: k +0 / +8
    const int bl7  = lane & 7;             // B: row within 8-n tile
    const int bk8  = ((lane >> 3) & 1) * 8;// B: k +0 / +8  (lanes 0-15 used)

    // ---- preload k-tile 0 into buf 0 ----
    {
        uint4 a0 = *(const uint4*)(gAh);     uint4 a1 = *(const uint4*)(gAh + 8);
        uint4 l0 = *(const uint4*)(gAl);     uint4 l1 = *(const uint4*)(gAl + 8);
        uint4 b0 = *(const uint4*)(gBh);     uint4 b1 = *(const uint4*)(gBh + 8);
        uint4 w0 = *(const uint4*)(gBl);     uint4 w1 = *(const uint4*)(gBl + 8);
        char* p = smraw;
        *(uint4*)(p + 0 * MATB + sdst) = a0;  *(uint4*)(p + 0 * MATB + sdst + 16) = a1;
        *(uint4*)(p + 1 * MATB + sdst) = l0;  *(uint4*)(p + 1 * MATB + sdst + 16) = l1;
        *(uint4*)(p + 2 * MATB + sdst) = b0;  *(uint4*)(p + 2 * MATB + sdst + 16) = b1;
        *(uint4*)(p + 3 * MATB + sdst) = w0;  *(uint4*)(p + 3 * MATB + sdst + 16) = w1;
    }
    __syncthreads();

    int buf = 0;
    for (int k0 = 32; k0 <= K; k0 += 32) {
        // prefetch next tile into registers
        uint4 a0, a1, l0, l1, b0, b1, w0, w1;
        const bool more = (k0 < K);
        if (more) {
            a0 = *(const uint4*)(gAh + k0); a1 = *(const uint4*)(gAh + k0 + 8);
            l0 = *(const uint4*)(gAl + k0); l1 = *(const uint4*)(gAl + k0 + 8);
            b0 = *(const uint4*)(gBh + k0); b1 = *(const uint4*)(gBh + k0 + 8);
            w0 = *(const uint4*)(gBl + k0); w1 = *(const uint4*)(gBl + k0 + 8);
        }

        // ---- compute on buf ----
        const uint32_t bb = sb + (uint32_t)buf * BUFB;
#pragma unroll
        for (int ks = 0; ks < 2; ks++) {
            uint32_t bh[4][2], bl[4][2];
#pragma unroll
            for (int nt = 0; nt < 4; nt++) {
                uint32_t boff = (uint32_t)((n0w + nt * 8 + bl7) * (BKP * 2)
                                           + (ks * 16 + bk8) * 2);
                LDSM2(bh[nt][0], bh[nt][1], bb + 2 * MATB + boff);
                LDSM2(bl[nt][0], bl[nt][1], bb + 3 * MATB + boff);
            }
#pragma unroll
            for (int mt = 0; mt < 4; mt++) {
                uint32_t aoff = (uint32_t)((m0w + mt * 16 + arow) * (BKP * 2)
                                           + (ks * 16 + acol) * 2);
                uint32_t ah[4], al[4];
                LDSM4(ah[0], ah[1], ah[2], ah[3], bb + 0 * MATB + aoff);
                LDSM4(al[0], al[1], al[2], al[3], bb + 1 * MATB + aoff);
#pragma unroll
                for (int nt = 0; nt < 4; nt++) {
                    MMA_BF16(c[mt][nt], ah, bh[nt]);
                    MMA_BF16(c[mt][nt], ah, bl[nt]);
                    MMA_BF16(c[mt][nt], al, bh[nt]);
                }
            }
        }

        // ---- store prefetched tile into the other buffer ----
        if (more) {
            char* p = smraw + (buf ^ 1) * BUFB;
            *(uint4*)(p + 0 * MATB + sdst) = a0;  *(uint4*)(p + 0 * MATB + sdst + 16) = a1;
            *(uint4*)(p + 1 * MATB + sdst) = l0;  *(uint4*)(p + 1 * MATB + sdst + 16) = l1;
            *(uint4*)(p + 2 * MATB + sdst) = b0;  *(uint4*)(p + 2 * MATB + sdst + 16) = b1;
            *(uint4*)(p + 3 * MATB + sdst) = w0;  *(uint4*)(p + 3 * MATB + sdst + 16) = w1;
            __syncthreads();
            buf ^= 1;
        }
    }

    // ---- epilogue ----
    const int erow = lane >> 2;
    const int ecol = (lane & 3) * 2;
#pragma unroll
    for (int mt = 0; mt < 4; mt++) {
#pragma unroll
        for (int nt = 0; nt < 4; nt++) {
            const int col = n0 + n0w + nt * 8 + ecol;
            const float bi0 = bias[col], bi1 = bias[col + 1];
            const int r0 = m0 + m0w + mt * 16 + erow;
            float2 v0, v1;
            v0.x = c[mt][nt][0] + bi0;  v0.y = c[mt][nt][1] + bi1;
            v1.x = c[mt][nt][2] + bi0;  v1.y = c[mt][nt][3] + bi1;
            *(float2*)(C + (size_t)r0 * N + col) = v0;
            *(float2*)(C + (size_t)(r0 + 8) * N + col) = v1;
        }
    }
}

// ---------------------------------------------------------------------------
// Flash attention (unchanged R9): 128q x 128k, 512 threads, double-buffered.
// ---------------------------------------------------------------------------
#define ATTN_SMEM_FLOATS (64 * 128 + 2 * 64 * 128 + 2 * 128 * 64 + 128 * 128)

__global__ __launch_bounds__(512, 1)
void attention_kernel(const float* __restrict__ qkv, float* __restrict__ out) {
    extern __shared__ float sm[];
    float* Qt  = sm;
    float* Kt0 = Qt + 64 * 128;
    float* Kt1 = Kt0 + 64 * 128;
    float* Vs0 = Kt1 + 64 * 128;
    float* Vs1 = Vs0 + 128 * 64;
    float* Ps  = Vs1 + 128 * 64;

    const int tid = threadIdx.x;
    const int tx  = tid & 15;
    const int ty  = tid >> 4;
    const int bh  = blockIdx.x;
    const int b   = bh >> 4;
    const int h   = bh & 15;
    const int q0  = blockIdx.y * 128;

    const float* base = qkv + (size_t)b * S_ * (3 * D_);
    const int qoff = h * HD_;
    const int koff = D_ + h * HD_;
    const int voff = 2 * D_ + h * HD_;

    const int lr = tid >> 2;
    const int lc = (tid & 3) * 16;
    const int g0 = lc >> 2;
    const int vsw = lr & 7;

    {
        const float* qp = base + (size_t)(q0 + lr) * (3 * D_) + qoff + lc;
        const float* kp = base + (size_t)lr * (3 * D_) + koff + lc;
        const float* vp = base + (size_t)lr * (3 * D_) + voff + lc;
#pragma unroll
        for (int i = 0; i < 4; i++) {
            float4 qv = *(const float4*)(qp + i * 4);
            Qt[(lc + i * 4 + 0) * 128 + lr] = qv.x;
            Qt[(lc + i * 4 + 1) * 128 + lr] = qv.y;
            Qt[(lc + i * 4 + 2) * 128 + lr] = qv.z;
            Qt[(lc + i * 4 + 3) * 128 + lr] = qv.w;
            float4 kv = *(const float4*)(kp + i * 4);
            Kt0[(lc + i * 4 + 0) * 128 + lr] = kv.x;
            Kt0[(lc + i * 4 + 1) * 128 + lr] = kv.y;
            Kt0[(lc + i * 4 + 2) * 128 + lr] = kv.z;
            Kt0[(lc + i * 4 + 3) * 128 + lr] = kv.w;
            *(float4*)&Vs0[lr * 64 + (((g0 + i) ^ vsw) << 2)] =
                *(const float4*)(vp + i * 4);
        }
    }
    __syncthreads();

    float m_i[4], l_i[4], o[4][4];
#pragma unroll
    for (int i = 0; i < 4; i++) {
        m_i[i] = -1e30f;
        l_i[i] = 0.f;
#pragma unroll
        for (int j = 0; j < 4; j++) o[i][j] = 0.f;
    }

    const float scale = 0.125f;
    int buf = 0;

    for (int kt = 0; kt < S_ / 128; kt++) {
        float4 kr[4], vr[4];
        const bool more = (kt + 1 < S_ / 128);
        if (more) {
            const float* rowp = base + (size_t)((kt + 1) * 128 + lr) * (3 * D_);
            const float* kp = rowp + koff + lc;
            const float* vp = rowp + voff + lc;
#pragma unroll
            for (int i = 0; i < 4; i++) {
                kr[i] = *(const float4*)(kp + i * 4);
                vr[i] = *(const float4*)(vp + i * 4);
            }
        }

        const float* Kt = buf ? Kt1 : Kt0;
        const float* Vs = buf ? Vs1 : Vs0;

        float s[2][4][4] = {};
#pragma unroll 8
        for (int dd = 0; dd < 64; dd++) {
            float4 a0 = *(const float4*)&Qt[dd * 128 + ty * 4];
            float4 b0 = *(const float4*)&Kt[dd * 128 + tx * 4];
            float4 b1 = *(const float4*)&Kt[dd * 128 + tx * 4 + 64];
            float ar[4] = {a0.x, a0.y, a0.z, a0.w};
            float br[2][4] = {{b0.x, b0.y, b0.z, b0.w}, {b1.x, b1.y, b1.z, b1.w}};
#pragma unroll
            for (int ki = 0; ki < 2; ki++)
#pragma unroll
                for (int i = 0; i < 4; i++)
#pragma unroll
                    for (int j = 0; j < 4; j++)
                        s[ki][i][j] += ar[i] * br[ki][j];
        }

#pragma unroll
        for (int i = 0; i < 4; i++) {
            const int row = ty * 4 + i;
            float mx = -1e30f;
#pragma unroll
            for (int ki = 0; ki < 2; ki++)
#pragma unroll
                for (int j = 0; j < 4; j++) {
                    s[ki][i][j] *= scale;
                    mx = fmaxf(mx, s[ki][i][j]);
                }
#pragma unroll
            for (int off = 8; off >= 1; off >>= 1)
                mx = fmaxf(mx, __shfl_xor_sync(0xffffffffu, mx, off));
            float m_new = fmaxf(m_i[i], mx);
            float alpha = __expf(m_i[i] - m_new);
            float rs = 0.f;
#pragma unroll
            for (int ki = 0; ki < 2; ki++) {
                float4 pv;
                pv.x = __expf(s[ki][i][0] - m_new);
                pv.y = __expf(s[ki][i][1] - m_new);
                pv.z = __expf(s[ki][i][2] - m_new);
                pv.w = __expf(s[ki][i][3] - m_new);
                rs += pv.x + pv.y + pv.z + pv.w;
                *(float4*)&Ps[row * 128 + tx * 4 + ki * 64] = pv;
            }
#pragma unroll
            for (int off = 8; off >= 1; off >>= 1)
                rs += __shfl_xor_sync(0xffffffffu, rs, off);
            l_i[i] = l_i[i] * alpha + rs;
            m_i[i] = m_new;
#pragma unroll
            for (int j = 0; j < 4; j++) o[i][j] *= alpha;
        }
        __syncwarp();

#pragma unroll 4
        for (int kk4 = 0; kk4 < 32; kk4++) {
            float4 vf[4];
#pragma unroll
            for (int t = 0; t < 4; t++) {
                const int kk = kk4 * 4 + t;
                vf[t] = *(const float4*)&Vs[kk * 64 + ((tx ^ (kk & 7)) << 2)];
            }
#pragma unroll
            for (int i = 0; i < 4; i++) {
                float4 pf = *(const float4*)&Ps[(ty * 4 + i) * 128 + kk4 * 4];
#pragma unroll
                for (int j = 0; j < 4; j++) {
                    o[i][j] += pf.x * ((const float*)&vf[0])[j]
                             + pf.y * ((const float*)&vf[1])[j]
                             + pf.z * ((const float*)&vf[2])[j]
                             + pf.w * ((const float*)&vf[3])[j];
                }
            }
        }

        if (more) {
            float* Ktn = buf ? Kt0 : Kt1;
            float* Vsn = buf ? Vs0 : Vs1;
#pragma unroll
            for (int i = 0; i < 4; i++) {
                Ktn[(lc + i * 4 + 0) * 128 + lr] = kr[i].x;
                Ktn[(lc + i * 4 + 1) * 128 + lr] = kr[i].y;
                Ktn[(lc + i * 4 + 2) * 128 + lr] = kr[i].z;
                Ktn[(lc + i * 4 + 3) * 128 + lr] = kr[i].w;
                *(float4*)&Vsn[lr * 64 + (((g0 + i) ^ vsw) << 2)] = vr[i];
            }
        }
        __syncthreads();
        buf ^= 1;
    }

#pragma unroll
    for (int i = 0; i < 4; i++) {
        const int q = q0 + ty * 4 + i;
        const float inv = 1.f / l_i[i];
        float4 v;
        v.x = o[i][0] * inv;
        v.y = o[i][1] * inv;
        v.z = o[i][2] * inv;
        v.w = o[i][3] * inv;
        *(float4*)(out + ((size_t)(b * S_ + q)) * D_ + h * HD_ + tx * 4) = v;
    }
}

// ---------------------------------------------------------------------------
extern "C" void kernel_launch(void* const* d_in, const int* in_sizes, int n_in,
                              void* d_out, int out_size) {
    const float* x     = (const float*)d_in[0];
    const float* Wqkv  = (const float*)d_in[1];
    const float* bqkv  = (const float*)d_in[2];
    const float* Wproj = (const float*)d_in[3];
    const float* bproj = (const float*)d_in[4];
    float* out = (float*)d_out;

    float *qkv, *att;
    __nv_bfloat16 *ahi, *alo, *bthi, *btlo;
    cudaGetSymbolAddress((void**)&qkv,  g_qkv);
    cudaGetSymbolAddress((void**)&att,  g_att);
    cudaGetSymbolAddress((void**)&ahi,  g_ahi);
    cudaGetSymbolAddress((void**)&alo,  g_alo);
    cudaGetSymbolAddress((void**)&bthi, g_bthi);
    cudaGetSymbolAddress((void**)&btlo, g_btlo);

    const int attn_smem = ATTN_SMEM_FLOATS * (int)sizeof(float);  // 229376
    cudaFuncSetAttribute(attention_kernel,
                         cudaFuncAttributeMaxDynamicSharedMemorySize, attn_smem);
    cudaFuncSetAttribute(gemm_bf16x3,
                         cudaFuncAttributeMaxDynamicSharedMemorySize, GEMM_SMEM);

    const int n4 = MTOT * D_ / 4;

    // 1) prep: split x; transpose+split Wqkv -> [3072][1024]
    split_bf16<<<(n4 + 255) / 256, 256>>>(x, ahi, alo, n4);
    transpose_split_bf16<<<dim3(3 * D_ / 32, D_ / 32), dim3(32, 8)>>>(
        Wqkv, bthi, btlo, D_, 3 * D_);

    // 2) QKV projection: [4096,1024] @ [1024,3072]
    gemm_bf16x3<<<dim3(3 * D_ / 128, MTOT / 128), 256, GEMM_SMEM>>>(
        ahi, alo, bthi, btlo, bqkv, qkv, MTOT, 3 * D_, D_);

    // 3) attention
    attention_kernel<<<dim3(B_ * H_, S_ / 128), 512, attn_smem>>>(qkv, att);

    // 4) prep: split att; transpose+split Wproj -> [1024][1024]
    split_bf16<<<(n4 + 255) / 256, 256>>>(att, ahi, alo, n4);
    transpose_split_bf16<<<dim3(D_ / 32, D_ / 32), dim3(32, 8)>>>(
        Wproj, bthi, btlo, D_, D_);

    // 5) output projection: [4096,1024] @ [1024,1024]
    gemm_bf16x3<<<dim3(D_ / 128, MTOT / 128), 256, GEMM_SMEM>>>(
        ahi, alo, bthi, btlo, bproj, out, MTOT, D_, D_);
}

// round 12
// speedup vs baseline: 2.2598x; 1.6976x over previous
#include <cuda_runtime.h>
#include <cuda_bf16.h>
#include <cstdint>
#include <math.h>

#define B_   2
#define S_   2048
#define D_   1024
#define H_   16
#define HD_  64
#define MTOT (B_ * S_)        // 4096

// Scratch (__device__ globals; no cudaMalloc allowed)
__device__ float g_qkv[MTOT * 3 * D_];            // 50 MB
__device__ float g_att[MTOT * D_];                // 17 MB
__device__ __nv_bfloat16 g_ahi[MTOT * D_];        // 8 MB
__device__ __nv_bfloat16 g_alo[MTOT * D_];        // 8 MB
__device__ __nv_bfloat16 g_bthi[3 * D_ * D_];     // 6 MB  (W^T, [N][K])
__device__ __nv_bfloat16 g_btlo[3 * D_ * D_];     // 6 MB

// ---------------------------------------------------------------------------
// helpers
// ---------------------------------------------------------------------------
__device__ __forceinline__ uint32_t smem_u32(const void* p) {
    uint32_t a;
    asm("{ .reg .u64 t; cvta.to.shared.u64 t, %1; cvt.u32.u64 %0, t; }"
        : "=r"(a) : "l"(p));
    return a;
}

#define LDSM4(r0, r1, r2, r3, addr) \
    asm volatile("ldmatrix.sync.aligned.m8n8.x4.shared.b16 {%0,%1,%2,%3}, [%4];" \
                 : "=r"(r0), "=r"(r1), "=r"(r2), "=r"(r3) : "r"(addr))
#define LDSM2(r0, r1, addr) \
    asm volatile("ldmatrix.sync.aligned.m8n8.x2.shared.b16 {%0,%1}, [%2];" \
                 : "=r"(r0), "=r"(r1) : "r"(addr))
#define LDSM2T(r0, r1, addr) \
    asm volatile("ldmatrix.sync.aligned.m8n8.x2.trans.shared.b16 {%0,%1}, [%2];" \
                 : "=r"(r0), "=r"(r1) : "r"(addr))

#define MMA_BF16(c, a, b) \
    asm volatile("mma.sync.aligned.m16n8k16.row.col.f32.bf16.bf16.f32 " \
                 "{%0,%1,%2,%3}, {%4,%5,%6,%7}, {%8,%9}, {%0,%1,%2,%3};" \
                 : "+f"((c)[0]), "+f"((c)[1]), "+f"((c)[2]), "+f"((c)[3]) \
                 : "r"((a)[0]), "r"((a)[1]), "r"((a)[2]), "r"((a)[3]), \
                   "r"((b)[0]), "r"((b)[1]))

__device__ __forceinline__ uint32_t pack_bf16(float a, float b) {
    __nv_bfloat162 t = __floats2bfloat162_rn(a, b);
    return *reinterpret_cast<uint32_t*>(&t);
}

// split a pair into hi bf16x2 + lo (residual) bf16x2
__device__ __forceinline__ void pack2_split(float a, float b,
                                            uint32_t& hi, uint32_t& lo) {
    __nv_bfloat162 h = __floats2bfloat162_rn(a, b);
    hi = *reinterpret_cast<uint32_t*>(&h);
    float ha = __bfloat162float(h.x), hb = __bfloat162float(h.y);
    __nv_bfloat162 l = __floats2bfloat162_rn(a - ha, b - hb);
    lo = *reinterpret_cast<uint32_t*>(&l);
}

// ---------------------------------------------------------------------------
// Prep: split fp32 -> bf16 hi/lo  (rowwise, [M][K] layout preserved)
// ---------------------------------------------------------------------------
__global__ void split_bf16(const float* __restrict__ src,
                           __nv_bfloat16* __restrict__ hi,
                           __nv_bfloat16* __restrict__ lo, int n4) {
    int i = blockIdx.x * blockDim.x + threadIdx.x;
    if (i >= n4) return;
    float4 v = ((const float4*)src)[i];
    float h0 = __bfloat162float(__float2bfloat16_rn(v.x));
    float h1 = __bfloat162float(__float2bfloat16_rn(v.y));
    float h2 = __bfloat162float(__float2bfloat16_rn(v.z));
    float h3 = __bfloat162float(__float2bfloat16_rn(v.w));
    uint2 ho, lw;
    ho.x = pack_bf16(h0, h1);
    ho.y = pack_bf16(h2, h3);
    lw.x = pack_bf16(v.x - h0, v.y - h1);
    lw.y = pack_bf16(v.z - h2, v.w - h3);
    ((uint2*)hi)[i] = ho;
    ((uint2*)lo)[i] = lw;
}

// Prep: W[K][N] fp32 -> W^T hi/lo bf16 [N][K]
__global__ void transpose_split_bf16(const float* __restrict__ W,
                                     __nv_bfloat16* __restrict__ Thi,
                                     __nv_bfloat16* __restrict__ Tlo,
                                     int K, int N) {
    __shared__ float t[32][33];
    int n0 = blockIdx.x * 32, k0 = blockIdx.y * 32;
    int tx = threadIdx.x, ty = threadIdx.y;   // 32 x 8
#pragma unroll
    for (int i = 0; i < 4; i++)
        t[ty + 8 * i][tx] = W[(size_t)(k0 + ty + 8 * i) * N + n0 + tx];
    __syncthreads();
#pragma unroll
    for (int i = 0; i < 4; i++) {
        float v = t[tx][ty + 8 * i];
        float h = __bfloat162float(__float2bfloat16_rn(v));
        size_t o = (size_t)(n0 + ty + 8 * i) * K + k0 + tx;
        Thi[o] = __float2bfloat16_rn(h);
        Tlo[o] = __float2bfloat16_rn(v - h);
    }
}

// ---------------------------------------------------------------------------
// Tensor-core GEMM (unchanged R10 winner): C = A @ W + bias, bf16 x3 split.
// ---------------------------------------------------------------------------
#define BKP 40
#define MATB (128 * BKP * 2)
#define BUFB (4 * MATB)
#define GEMM_SMEM (2 * BUFB)

__global__ __launch_bounds__(256, 1)
void gemm_bf16x3(const __nv_bfloat16* __restrict__ Ahi,
                 const __nv_bfloat16* __restrict__ Alo,
                 const __nv_bfloat16* __restrict__ Bhi,
                 const __nv_bfloat16* __restrict__ Blo,
                 const float* __restrict__ bias, float* __restrict__ C,
                 int M, int N, int K) {
    extern __shared__ char smraw[];
    const int tid  = threadIdx.x;
    const int lane = tid & 31;
    const int wid  = tid >> 5;
    const int m0   = blockIdx.y * 128;
    const int n0   = blockIdx.x * 128;
    const int m0w  = (wid >> 2) * 64;
    const int n0w  = (wid & 3) * 32;
    const uint32_t sb = smem_u32(smraw);

    const int lrow = tid >> 1;
    const int lk   = (tid & 1) * 16;
    const __nv_bfloat16* gAh = Ahi + (size_t)(m0 + lrow) * K + lk;
    const __nv_bfloat16* gAl = Alo + (size_t)(m0 + lrow) * K + lk;
    const __nv_bfloat16* gBh = Bhi + (size_t)(n0 + lrow) * K + lk;
    const __nv_bfloat16* gBl = Blo + (size_t)(n0 + lrow) * K + lk;
    const uint32_t sdst = (uint32_t)(lrow * (BKP * 2) + lk * 2);

    float c[4][4][4] = {};

    const int arow = lane & 15;
    const int acol = (lane >> 4) * 8;
    const int bl7  = lane & 7;
    const int bk8  = ((lane >> 3) & 1) * 8;

    {
        uint4 a0 = *(const uint4*)(gAh);     uint4 a1 = *(const uint4*)(gAh + 8);
        uint4 l0 = *(const uint4*)(gAl);     uint4 l1 = *(const uint4*)(gAl + 8);
        uint4 b0 = *(const uint4*)(gBh);     uint4 b1 = *(const uint4*)(gBh + 8);
        uint4 w0 = *(const uint4*)(gBl);     uint4 w1 = *(const uint4*)(gBl + 8);
        char* p = smraw;
        *(uint4*)(p + 0 * MATB + sdst) = a0;  *(uint4*)(p + 0 * MATB + sdst + 16) = a1;
        *(uint4*)(p + 1 * MATB + sdst) = l0;  *(uint4*)(p + 1 * MATB + sdst + 16) = l1;
        *(uint4*)(p + 2 * MATB + sdst) = b0;  *(uint4*)(p + 2 * MATB + sdst + 16) = b1;
        *(uint4*)(p + 3 * MATB + sdst) = w0;  *(uint4*)(p + 3 * MATB + sdst + 16) = w1;
    }
    __syncthreads();

    int buf = 0;
    for (int k0 = 32; k0 <= K; k0 += 32) {
        uint4 a0, a1, l0, l1, b0, b1, w0, w1;
        const bool more = (k0 < K);
        if (more) {
            a0 = *(const uint4*)(gAh + k0); a1 = *(const uint4*)(gAh + k0 + 8);
            l0 = *(const uint4*)(gAl + k0); l1 = *(const uint4*)(gAl + k0 + 8);
            b0 = *(const uint4*)(gBh + k0); b1 = *(const uint4*)(gBh + k0 + 8);
            w0 = *(const uint4*)(gBl + k0); w1 = *(const uint4*)(gBl + k0 + 8);
        }

        const uint32_t bb = sb + (uint32_t)buf * BUFB;
#pragma unroll
        for (int ks = 0; ks < 2; ks++) {
            uint32_t bh[4][2], bl[4][2];
#pragma unroll
            for (int nt = 0; nt < 4; nt++) {
                uint32_t boff = (uint32_t)((n0w + nt * 8 + bl7) * (BKP * 2)
                                           + (ks * 16 + bk8) * 2);
                LDSM2(bh[nt][0], bh[nt][1], bb + 2 * MATB + boff);
                LDSM2(bl[nt][0], bl[nt][1], bb + 3 * MATB + boff);
            }
#pragma unroll
            for (int mt = 0; mt < 4; mt++) {
                uint32_t aoff = (uint32_t)((m0w + mt * 16 + arow) * (BKP * 2)
                                           + (ks * 16 + acol) * 2);
                uint32_t ah[4], al[4];
                LDSM4(ah[0], ah[1], ah[2], ah[3], bb + 0 * MATB + aoff);
                LDSM4(al[0], al[1], al[2], al[3], bb + 1 * MATB + aoff);
#pragma unroll
                for (int nt = 0; nt < 4; nt++) {
                    MMA_BF16(c[mt][nt], ah, bh[nt]);
                    MMA_BF16(c[mt][nt], ah, bl[nt]);
                    MMA_BF16(c[mt][nt], al, bh[nt]);
                }
            }
        }

        if (more) {
            char* p = smraw + (buf ^ 1) * BUFB;
            *(uint4*)(p + 0 * MATB + sdst) = a0;  *(uint4*)(p + 0 * MATB + sdst + 16) = a1;
            *(uint4*)(p + 1 * MATB + sdst) = l0;  *(uint4*)(p + 1 * MATB + sdst + 16) = l1;
            *(uint4*)(p + 2 * MATB + sdst) = b0;  *(uint4*)(p + 2 * MATB + sdst + 16) = b1;
            *(uint4*)(p + 3 * MATB + sdst) = w0;  *(uint4*)(p + 3 * MATB + sdst + 16) = w1;
            __syncthreads();
            buf ^= 1;
        }
    }

    const int erow = lane >> 2;
    const int ecol = (lane & 3) * 2;
#pragma unroll
    for (int mt = 0; mt < 4; mt++) {
#pragma unroll
        for (int nt = 0; nt < 4; nt++) {
            const int col = n0 + n0w + nt * 8 + ecol;
            const float bi0 = bias[col], bi1 = bias[col + 1];
            const int r0 = m0 + m0w + mt * 16 + erow;
            float2 v0, v1;
            v0.x = c[mt][nt][0] + bi0;  v0.y = c[mt][nt][1] + bi1;
            v1.x = c[mt][nt][2] + bi0;  v1.y = c[mt][nt][3] + bi1;
            *(float2*)(C + (size_t)r0 * N + col) = v0;
            *(float2*)(C + (size_t)(r0 + 8) * N + col) = v1;
        }
    }
}

// ---------------------------------------------------------------------------
// Tensor-core flash attention. 256 threads (8 warps), tile 128q x 128k.
// Warp w owns q rows w*16..w*16+15 (full 128 k cols).
// QK^T and PV via mma.m16n8k16 bf16 hi/lo 3-term split (err ~1e-5).
// P never touches smem: S fragments -> exp -> repacked as A fragments.
// V stored [k][d] bf16 (hi/lo), fed via ldmatrix.x2.trans.
// smem: Qh,Ql,Kh,Kl,Vh,Vl each [128][72] bf16 = 110592 B total.
// ---------------------------------------------------------------------------
#define QP 72
#define ATTN_SMEM (6 * 128 * QP * 2)     // 110592 bytes

__global__ __launch_bounds__(256, 1)
void attention_mma(const float* __restrict__ qkv, float* __restrict__ out) {
    extern __shared__ __nv_bfloat16 smb[];
    __nv_bfloat16* Qh = smb;
    __nv_bfloat16* Ql = Qh + 128 * QP;
    __nv_bfloat16* Kh = Ql + 128 * QP;
    __nv_bfloat16* Kl = Kh + 128 * QP;
    __nv_bfloat16* Vh = Kl + 128 * QP;
    __nv_bfloat16* Vl = Vh + 128 * QP;

    const int tid  = threadIdx.x;
    const int lane = tid & 31;
    const int wid  = tid >> 5;
    const int l16  = lane & 15;
    const int qr0  = wid * 16;            // warp's q-row base in tile

    const int b  = blockIdx.x >> 4;
    const int h  = blockIdx.x & 15;
    const int q0 = blockIdx.y * 128;

    const float* base = qkv + (size_t)b * S_ * (3 * D_);
    const int qoff = h * HD_;
    const int koff = D_ + h * HD_;
    const int voff = 2 * D_ + h * HD_;

    // loader mapping: row lr = tid>>1 (0..127), d-half lc = (tid&1)*32
    const int lr = tid >> 1;
    const int lc = (tid & 1) * 32;

    // ---- load+convert Q tile ----
    {
        const float* qp = base + (size_t)(q0 + lr) * (3 * D_) + qoff + lc;
        __nv_bfloat16* dh = Qh + lr * QP + lc;
        __nv_bfloat16* dl = Ql + lr * QP + lc;
#pragma unroll
        for (int i = 0; i < 8; i++) {
            float4 v = *(const float4*)(qp + i * 4);
            float h0 = __bfloat162float(__float2bfloat16_rn(v.x));
            float h1 = __bfloat162float(__float2bfloat16_rn(v.y));
            float h2 = __bfloat162float(__float2bfloat16_rn(v.z));
            float h3 = __bfloat162float(__float2bfloat16_rn(v.w));
            uint2 hw, lw;
            hw.x = pack_bf16(h0, h1);          hw.y = pack_bf16(h2, h3);
            lw.x = pack_bf16(v.x - h0, v.y - h1); lw.y = pack_bf16(v.z - h2, v.w - h3);
            *(uint2*)(dh + i * 4) = hw;
            *(uint2*)(dl + i * 4) = lw;
        }
    }
    __syncthreads();

    // ---- Q fragments (persistent) ----
    uint32_t qh[4][4], ql[4][4];
#pragma unroll
    for (int ks = 0; ks < 4; ks++) {
        uint32_t ao = (uint32_t)((qr0 + (lane & 15)) * QP + ks * 16 + (lane >> 4) * 8) * 2;
        LDSM4(qh[ks][0], qh[ks][1], qh[ks][2], qh[ks][3], smem_u32(Qh) + ao);
        LDSM4(ql[ks][0], ql[ks][1], ql[ks][2], ql[ks][3], smem_u32(Ql) + ao);
    }

    float O[8][4] = {};
    float m0 = -1e30f, m1 = -1e30f, l0 = 0.f, l1 = 0.f;
    const float scale = 0.125f;

    const uint32_t kb_h = smem_u32(Kh) + (uint32_t)((l16 & 7) * QP + (l16 >> 3) * 8) * 2;
    const uint32_t kb_l = smem_u32(Kl) + (uint32_t)((l16 & 7) * QP + (l16 >> 3) * 8) * 2;
    const uint32_t vb_h = smem_u32(Vh) + (uint32_t)(l16 * QP) * 2;
    const uint32_t vb_l = smem_u32(Vl) + (uint32_t)(l16 * QP) * 2;

    for (int kt = 0; kt < S_ / 128; kt++) {
        // ---- load+convert K,V tile ----
        {
            const float* rowp = base + (size_t)(kt * 128 + lr) * (3 * D_);
            const float* kp = rowp + koff + lc;
            const float* vp = rowp + voff + lc;
            __nv_bfloat16* dkh = Kh + lr * QP + lc;
            __nv_bfloat16* dkl = Kl + lr * QP + lc;
            __nv_bfloat16* dvh = Vh + lr * QP + lc;
            __nv_bfloat16* dvl = Vl + lr * QP + lc;
#pragma unroll
            for (int i = 0; i < 8; i++) {
                float4 v = *(const float4*)(kp + i * 4);
                float h0 = __bfloat162float(__float2bfloat16_rn(v.x));
                float h1 = __bfloat162float(__float2bfloat16_rn(v.y));
                float h2 = __bfloat162float(__float2bfloat16_rn(v.z));
                float h3 = __bfloat162float(__float2bfloat16_rn(v.w));
                uint2 hw, lw;
                hw.x = pack_bf16(h0, h1);             hw.y = pack_bf16(h2, h3);
                lw.x = pack_bf16(v.x - h0, v.y - h1); lw.y = pack_bf16(v.z - h2, v.w - h3);
                *(uint2*)(dkh + i * 4) = hw;
                *(uint2*)(dkl + i * 4) = lw;
                float4 w = *(const float4*)(vp + i * 4);
                float g0 = __bfloat162float(__float2bfloat16_rn(w.x));
                float g1 = __bfloat162float(__float2bfloat16_rn(w.y));
                float g2 = __bfloat162float(__float2bfloat16_rn(w.z));
                float g3 = __bfloat162float(__float2bfloat16_rn(w.w));
                uint2 vw, ww;
                vw.x = pack_bf16(g0, g1);             vw.y = pack_bf16(g2, g3);
                ww.x = pack_bf16(w.x - g0, w.y - g1); ww.y = pack_bf16(w.z - g2, w.w - g3);
                *(uint2*)(dvh + i * 4) = vw;
                *(uint2*)(dvl + i * 4) = ww;
            }
        }
        __syncthreads();

        // ---- S = QK^T (3-term split) ----
        float s[16][4];
#pragma unroll
        for (int nf = 0; nf < 16; nf++) {
            s[nf][0] = s[nf][1] = s[nf][2] = s[nf][3] = 0.f;
#pragma unroll
            for (int ks = 0; ks < 4; ks++) {
                const uint32_t off = (uint32_t)(nf * 8 * QP + ks * 16) * 2;
                uint32_t bh[2], bl[2];
                LDSM2(bh[0], bh[1], kb_h + off);
                LDSM2(bl[0], bl[1], kb_l + off);
                MMA_BF16(s[nf], qh[ks], bh);
                MMA_BF16(s[nf], qh[ks], bl);
                MMA_BF16(s[nf], ql[ks], bh);
            }
        }

        // ---- online softmax on fragments ----
        float mx0 = -1e30f, mx1 = -1e30f;
#pragma unroll
        for (int nf = 0; nf < 16; nf++) {
            s[nf][0] *= scale; s[nf][1] *= scale;
            s[nf][2] *= scale; s[nf][3] *= scale;
            mx0 = fmaxf(mx0, fmaxf(s[nf][0], s[nf][1]));
            mx1 = fmaxf(mx1, fmaxf(s[nf][2], s[nf][3]));
        }
        mx0 = fmaxf(mx0, __shfl_xor_sync(0xffffffffu, mx0, 1));
        mx0 = fmaxf(mx0, __shfl_xor_sync(0xffffffffu, mx0, 2));
        mx1 = fmaxf(mx1, __shfl_xor_sync(0xffffffffu, mx1, 1));
        mx1 = fmaxf(mx1, __shfl_xor_sync(0xffffffffu, mx1, 2));

        const float mn0 = fmaxf(m0, mx0);
        const float mn1 = fmaxf(m1, mx1);
        const float al0 = __expf(m0 - mn0);
        const float al1 = __expf(m1 - mn1);
        m0 = mn0; m1 = mn1;

        float rs0 = 0.f, rs1 = 0.f;
#pragma unroll
        for (int nf = 0; nf < 16; nf++) {
            s[nf][0] = __expf(s[nf][0] - m0);
            s[nf][1] = __expf(s[nf][1] - m0);
            s[nf][2] = __expf(s[nf][2] - m1);
            s[nf][3] = __expf(s[nf][3] - m1);
            rs0 += s[nf][0] + s[nf][1];
            rs1 += s[nf][2] + s[nf][3];
        }
        rs0 += __shfl_xor_sync(0xffffffffu, rs0, 1);
        rs0 += __shfl_xor_sync(0xffffffffu, rs0, 2);
        rs1 += __shfl_xor_sync(0xffffffffu, rs1, 1);
        rs1 += __shfl_xor_sync(0xffffffffu, rs1, 2);
        l0 = l0 * al0 + rs0;
        l1 = l1 * al1 + rs1;

#pragma unroll
        for (int df = 0; df < 8; df++) {
            O[df][0] *= al0; O[df][1] *= al0;
            O[df][2] *= al1; O[df][3] *= al1;
        }

        // ---- O += P @ V (3-term split; P direct from registers) ----
#pragma unroll
        for (int kk = 0; kk < 8; kk++) {
            uint32_t ah[4], alr[4];
            pack2_split(s[2 * kk][0],     s[2 * kk][1],     ah[0], alr[0]);
            pack2_split(s[2 * kk][2],     s[2 * kk][3],     ah[1], alr[1]);
            pack2_split(s[2 * kk + 1][0], s[2 * kk + 1][1], ah[2], alr[2]);
            pack2_split(s[2 * kk + 1][2], s[2 * kk + 1][3], ah[3], alr[3]);
#pragma unroll
            for (int df = 0; df < 8; df++) {
                const uint32_t off = (uint32_t)(kk * 16 * QP + df * 8) * 2;
                uint32_t vb[2], vl2[2];
                LDSM2T(vb[0],  vb[1],  vb_h + off);
                LDSM2T(vl2[0], vl2[1], vb_l + off);
                MMA_BF16(O[df], ah,  vb);
                MMA_BF16(O[df], ah,  vl2);
                MMA_BF16(O[df], alr, vb);
            }
        }
        __syncthreads();
    }

    // ---- epilogue: normalize + store fp32 ----
    const float inv0 = 1.f / l0;
    const float inv1 = 1.f / l1;
    const int qrow = q0 + qr0 + (lane >> 2);
    const int cb   = h * HD_ + (lane & 3) * 2;
#pragma unroll
    for (int df = 0; df < 8; df++) {
        float2 v0, v1;
        v0.x = O[df][0] * inv0;  v0.y = O[df][1] * inv0;
        v1.x = O[df][2] * inv1;  v1.y = O[df][3] * inv1;
        *(float2*)(out + (size_t)(b * S_ + qrow) * D_ + cb + df * 8) = v0;
        *(float2*)(out + (size_t)(b * S_ + qrow + 8) * D_ + cb + df * 8) = v1;
    }
}

// ---------------------------------------------------------------------------
extern "C" void kernel_launch(void* const* d_in, const int* in_sizes, int n_in,
                              void* d_out, int out_size) {
    const float* x     = (const float*)d_in[0];
    const float* Wqkv  = (const float*)d_in[1];
    const float* bqkv  = (const float*)d_in[2];
    const float* Wproj = (const float*)d_in[3];
    const float* bproj = (const float*)d_in[4];
    float* out = (float*)d_out;

    float *qkv, *att;
    __nv_bfloat16 *ahi, *alo, *bthi, *btlo;
    cudaGetSymbolAddress((void**)&qkv,  g_qkv);
    cudaGetSymbolAddress((void**)&att,  g_att);
    cudaGetSymbolAddress((void**)&ahi,  g_ahi);
    cudaGetSymbolAddress((void**)&alo,  g_alo);
    cudaGetSymbolAddress((void**)&bthi, g_bthi);
    cudaGetSymbolAddress((void**)&btlo, g_btlo);

    cudaFuncSetAttribute(attention_mma,
                         cudaFuncAttributeMaxDynamicSharedMemorySize, ATTN_SMEM);
    cudaFuncSetAttribute(gemm_bf16x3,
                         cudaFuncAttributeMaxDynamicSharedMemorySize, GEMM_SMEM);

    const int n4 = MTOT * D_ / 4;

    // 1) prep: split x; transpose+split Wqkv -> [3072][1024]
    split_bf16<<<(n4 + 255) / 256, 256>>>(x, ahi, alo, n4);
    transpose_split_bf16<<<dim3(3 * D_ / 32, D_ / 32), dim3(32, 8)>>>(
        Wqkv, bthi, btlo, D_, 3 * D_);

    // 2) QKV projection: [4096,1024] @ [1024,3072]
    gemm_bf16x3<<<dim3(3 * D_ / 128, MTOT / 128), 256, GEMM_SMEM>>>(
        ahi, alo, bthi, btlo, bqkv, qkv, MTOT, 3 * D_, D_);

    // 3) attention (tensor-core)
    attention_mma<<<dim3(B_ * H_, S_ / 128), 256, ATTN_SMEM>>>(qkv, att);

    // 4) prep: split att; transpose+split Wproj -> [1024][1024]
    split_bf16<<<(n4 + 255) / 256, 256>>>(att, ahi, alo, n4);
    transpose_split_bf16<<<dim3(D_ / 32, D_ / 32), dim3(32, 8)>>>(
        Wproj, bthi, btlo, D_, D_);

    // 5) output projection: [4096,1024] @ [1024,1024]
    gemm_bf16x3<<<dim3(D_ / 128, MTOT / 128), 256, GEMM_SMEM>>>(
        ahi, alo, bthi, btlo, bproj, out, MTOT, D_, D_);
}

// round 13
// speedup vs baseline: 2.5047x; 1.1084x over previous
#include <cuda_runtime.h>
#include <cuda_bf16.h>
#include <cstdint>
#include <math.h>

#define B_   2
#define S_   2048
#define D_   1024
#define H_   16
#define HD_  64
#define MTOT (B_ * S_)        // 4096

// Scratch (__device__ globals; no cudaMalloc allowed)
__device__ __nv_bfloat16 g_qkvh[MTOT * 3 * D_];   // qkv hi  (25 MB)
__device__ __nv_bfloat16 g_qkvl[MTOT * 3 * D_];   // qkv lo  (25 MB)
__device__ __nv_bfloat16 g_ahi[MTOT * D_];        // A-split hi (x, then att out)
__device__ __nv_bfloat16 g_alo[MTOT * D_];        // A-split lo
__device__ __nv_bfloat16 g_bthi[3 * D_ * D_];     // W^T hi [N][K]
__device__ __nv_bfloat16 g_btlo[3 * D_ * D_];     // W^T lo

// ---------------------------------------------------------------------------
// helpers
// ---------------------------------------------------------------------------
__device__ __forceinline__ uint32_t smem_u32(const void* p) {
    uint32_t a;
    asm("{ .reg .u64 t; cvta.to.shared.u64 t, %1; cvt.u32.u64 %0, t; }"
        : "=r"(a) : "l"(p));
    return a;
}

#define LDSM4(r0, r1, r2, r3, addr) \
    asm volatile("ldmatrix.sync.aligned.m8n8.x4.shared.b16 {%0,%1,%2,%3}, [%4];" \
                 : "=r"(r0), "=r"(r1), "=r"(r2), "=r"(r3) : "r"(addr))
#define LDSM2(r0, r1, addr) \
    asm volatile("ldmatrix.sync.aligned.m8n8.x2.shared.b16 {%0,%1}, [%2];" \
                 : "=r"(r0), "=r"(r1) : "r"(addr))
#define LDSM2T(r0, r1, addr) \
    asm volatile("ldmatrix.sync.aligned.m8n8.x2.trans.shared.b16 {%0,%1}, [%2];" \
                 : "=r"(r0), "=r"(r1) : "r"(addr))

#define MMA_BF16(c, a, b) \
    asm volatile("mma.sync.aligned.m16n8k16.row.col.f32.bf16.bf16.f32 " \
                 "{%0,%1,%2,%3}, {%4,%5,%6,%7}, {%8,%9}, {%0,%1,%2,%3};" \
                 : "+f"((c)[0]), "+f"((c)[1]), "+f"((c)[2]), "+f"((c)[3]) \
                 : "r"((a)[0]), "r"((a)[1]), "r"((a)[2]), "r"((a)[3]), \
                   "r"((b)[0]), "r"((b)[1]))

#define CP16(dst, src) \
    asm volatile("cp.async.cg.shared.global [%0], [%1], 16;" \
                 :: "r"(dst), "l"(src))
#define CP_COMMIT() asm volatile("cp.async.commit_group;" ::: "memory")
#define CP_WAIT0()  asm volatile("cp.async.wait_group 0;" ::: "memory")

__device__ __forceinline__ uint32_t pack_bf16(float a, float b) {
    __nv_bfloat162 t = __floats2bfloat162_rn(a, b);
    return *reinterpret_cast<uint32_t*>(&t);
}

// split a pair into hi bf16x2 + lo (residual) bf16x2
__device__ __forceinline__ void pack2_split(float a, float b,
                                            uint32_t& hi, uint32_t& lo) {
    __nv_bfloat162 h = __floats2bfloat162_rn(a, b);
    hi = *reinterpret_cast<uint32_t*>(&h);
    float ha = __bfloat162float(h.x), hb = __bfloat162float(h.y);
    __nv_bfloat162 l = __floats2bfloat162_rn(a - ha, b - hb);
    lo = *reinterpret_cast<uint32_t*>(&l);
}

// ---------------------------------------------------------------------------
// Prep: split fp32 -> bf16 hi/lo  (rowwise, [M][K] layout preserved)
// ---------------------------------------------------------------------------
__global__ void split_bf16(const float* __restrict__ src,
                           __nv_bfloat16* __restrict__ hi,
                           __nv_bfloat16* __restrict__ lo, int n4) {
    int i = blockIdx.x * blockDim.x + threadIdx.x;
    if (i >= n4) return;
    float4 v = ((const float4*)src)[i];
    float h0 = __bfloat162float(__float2bfloat16_rn(v.x));
    float h1 = __bfloat162float(__float2bfloat16_rn(v.y));
    float h2 = __bfloat162float(__float2bfloat16_rn(v.z));
    float h3 = __bfloat162float(__float2bfloat16_rn(v.w));
    uint2 ho, lw;
    ho.x = pack_bf16(h0, h1);
    ho.y = pack_bf16(h2, h3);
    lw.x = pack_bf16(v.x - h0, v.y - h1);
    lw.y = pack_bf16(v.z - h2, v.w - h3);
    ((uint2*)hi)[i] = ho;
    ((uint2*)lo)[i] = lw;
}

// Prep: W[K][N] fp32 -> W^T hi/lo bf16 [N][K]
__global__ void transpose_split_bf16(const float* __restrict__ W,
                                     __nv_bfloat16* __restrict__ Thi,
                                     __nv_bfloat16* __restrict__ Tlo,
                                     int K, int N) {
    __shared__ float t[32][33];
    int n0 = blockIdx.x * 32, k0 = blockIdx.y * 32;
    int tx = threadIdx.x, ty = threadIdx.y;   // 32 x 8
#pragma unroll
    for (int i = 0; i < 4; i++)
        t[ty + 8 * i][tx] = W[(size_t)(k0 + ty + 8 * i) * N + n0 + tx];
    __syncthreads();
#pragma unroll
    for (int i = 0; i < 4; i++) {
        float v = t[tx][ty + 8 * i];
        float h = __bfloat162float(__float2bfloat16_rn(v));
        size_t o = (size_t)(n0 + ty + 8 * i) * K + k0 + tx;
        Thi[o] = __float2bfloat16_rn(h);
        Tlo[o] = __float2bfloat16_rn(v - h);
    }
}

// ---------------------------------------------------------------------------
// Tensor-core GEMM: C = A @ W + bias, bf16 x3 split.
// SPLIT=true: write result as bf16 hi/lo pair (Chi/Clo); else fp32 C.
// ---------------------------------------------------------------------------
#define BKP 40
#define MATB (128 * BKP * 2)
#define BUFB (4 * MATB)
#define GEMM_SMEM (2 * BUFB)

template <bool SPLIT>
__global__ __launch_bounds__(256, 1)
void gemm_bf16x3(const __nv_bfloat16* __restrict__ Ahi,
                 const __nv_bfloat16* __restrict__ Alo,
                 const __nv_bfloat16* __restrict__ Bhi,
                 const __nv_bfloat16* __restrict__ Blo,
                 const float* __restrict__ bias, float* __restrict__ C,
                 __nv_bfloat16* __restrict__ Chi,
                 __nv_bfloat16* __restrict__ Clo,
                 int M, int N, int K) {
    extern __shared__ char smraw[];
    const int tid  = threadIdx.x;
    const int lane = tid & 31;
    const int wid  = tid >> 5;
    const int m0   = blockIdx.y * 128;
    const int n0   = blockIdx.x * 128;
    const int m0w  = (wid >> 2) * 64;
    const int n0w  = (wid & 3) * 32;
    const uint32_t sb = smem_u32(smraw);

    const int lrow = tid >> 1;
    const int lk   = (tid & 1) * 16;
    const __nv_bfloat16* gAh = Ahi + (size_t)(m0 + lrow) * K + lk;
    const __nv_bfloat16* gAl = Alo + (size_t)(m0 + lrow) * K + lk;
    const __nv_bfloat16* gBh = Bhi + (size_t)(n0 + lrow) * K + lk;
    const __nv_bfloat16* gBl = Blo + (size_t)(n0 + lrow) * K + lk;
    const uint32_t sdst = (uint32_t)(lrow * (BKP * 2) + lk * 2);

    float c[4][4][4] = {};

    const int arow = lane & 15;
    const int acol = (lane >> 4) * 8;
    const int bl7  = lane & 7;
    const int bk8  = ((lane >> 3) & 1) * 8;

    {
        uint4 a0 = *(const uint4*)(gAh);     uint4 a1 = *(const uint4*)(gAh + 8);
        uint4 l0 = *(const uint4*)(gAl);     uint4 l1 = *(const uint4*)(gAl + 8);
        uint4 b0 = *(const uint4*)(gBh);     uint4 b1 = *(const uint4*)(gBh + 8);
        uint4 w0 = *(const uint4*)(gBl);     uint4 w1 = *(const uint4*)(gBl + 8);
        char* p = smraw;
        *(uint4*)(p + 0 * MATB + sdst) = a0;  *(uint4*)(p + 0 * MATB + sdst + 16) = a1;
        *(uint4*)(p + 1 * MATB + sdst) = l0;  *(uint4*)(p + 1 * MATB + sdst + 16) = l1;
        *(uint4*)(p + 2 * MATB + sdst) = b0;  *(uint4*)(p + 2 * MATB + sdst + 16) = b1;
        *(uint4*)(p + 3 * MATB + sdst) = w0;  *(uint4*)(p + 3 * MATB + sdst + 16) = w1;
    }
    __syncthreads();

    int buf = 0;
    for (int k0 = 32; k0 <= K; k0 += 32) {
        uint4 a0, a1, l0, l1, b0, b1, w0, w1;
        const bool more = (k0 < K);
        if (more) {
            a0 = *(const uint4*)(gAh + k0); a1 = *(const uint4*)(gAh + k0 + 8);
            l0 = *(const uint4*)(gAl + k0); l1 = *(const uint4*)(gAl + k0 + 8);
            b0 = *(const uint4*)(gBh + k0); b1 = *(const uint4*)(gBh + k0 + 8);
            w0 = *(const uint4*)(gBl + k0); w1 = *(const uint4*)(gBl + k0 + 8);
        }

        const uint32_t bb = sb + (uint32_t)buf * BUFB;
#pragma unroll
        for (int ks = 0; ks < 2; ks++) {
            uint32_t bh[4][2], bl[4][2];
#pragma unroll
            for (int nt = 0; nt < 4; nt++) {
                uint32_t boff = (uint32_t)((n0w + nt * 8 + bl7) * (BKP * 2)
                                           + (ks * 16 + bk8) * 2);
                LDSM2(bh[nt][0], bh[nt][1], bb + 2 * MATB + boff);
                LDSM2(bl[nt][0], bl[nt][1], bb + 3 * MATB + boff);
            }
#pragma unroll
            for (int mt = 0; mt < 4; mt++) {
                uint32_t aoff = (uint32_t)((m0w + mt * 16 + arow) * (BKP * 2)
                                           + (ks * 16 + acol) * 2);
                uint32_t ah[4], al[4];
                LDSM4(ah[0], ah[1], ah[2], ah[3], bb + 0 * MATB + aoff);
                LDSM4(al[0], al[1], al[2], al[3], bb + 1 * MATB + aoff);
#pragma unroll
                for (int nt = 0; nt < 4; nt++) {
                    MMA_BF16(c[mt][nt], ah, bh[nt]);
                    MMA_BF16(c[mt][nt], ah, bl[nt]);
                    MMA_BF16(c[mt][nt], al, bh[nt]);
                }
            }
        }

        if (more) {
            char* p = smraw + (buf ^ 1) * BUFB;
            *(uint4*)(p + 0 * MATB + sdst) = a0;  *(uint4*)(p + 0 * MATB + sdst + 16) = a1;
            *(uint4*)(p + 1 * MATB + sdst) = l0;  *(uint4*)(p + 1 * MATB + sdst + 16) = l1;
            *(uint4*)(p + 2 * MATB + sdst) = b0;  *(uint4*)(p + 2 * MATB + sdst + 16) = b1;
            *(uint4*)(p + 3 * MATB + sdst) = w0;  *(uint4*)(p + 3 * MATB + sdst + 16) = w1;
            __syncthreads();
            buf ^= 1;
        }
    }

    const int erow = lane >> 2;
    const int ecol = (lane & 3) * 2;
#pragma unroll
    for (int mt = 0; mt < 4; mt++) {
#pragma unroll
        for (int nt = 0; nt < 4; nt++) {
            const int col = n0 + n0w + nt * 8 + ecol;
            const float bi0 = bias[col], bi1 = bias[col + 1];
            const int r0 = m0 + m0w + mt * 16 + erow;
            float v00 = c[mt][nt][0] + bi0, v01 = c[mt][nt][1] + bi1;
            float v10 = c[mt][nt][2] + bi0, v11 = c[mt][nt][3] + bi1;
            if (SPLIT) {
                uint32_t h0, l0v, h1, l1v;
                pack2_split(v00, v01, h0, l0v);
                pack2_split(v10, v11, h1, l1v);
                *(uint32_t*)(Chi + (size_t)r0 * N + col) = h0;
                *(uint32_t*)(Clo + (size_t)r0 * N + col) = l0v;
                *(uint32_t*)(Chi + (size_t)(r0 + 8) * N + col) = h1;
                *(uint32_t*)(Clo + (size_t)(r0 + 8) * N + col) = l1v;
            } else {
                float2 v0, v1;
                v0.x = v00; v0.y = v01;
                v1.x = v10; v1.y = v11;
                *(float2*)(C + (size_t)r0 * N + col) = v0;
                *(float2*)(C + (size_t)(r0 + 8) * N + col) = v1;
            }
        }
    }
}

// ---------------------------------------------------------------------------
// Tensor-core flash attention v2: inputs pre-split bf16 hi/lo (no in-kernel
// conversion). cp.async loaders, double-buffered K/V, one sync per tile.
// 256 threads (8 warps), tile 128q x 128k; warp w owns q rows w*16..+15.
// Output written directly as bf16 hi/lo (A operand of the proj GEMM).
// smem: Qh,Ql + 2 x (Kh,Kl,Vh,Vl), each [128][72] bf16 = 184320 B.
// ---------------------------------------------------------------------------
#define QP 72
#define TILEB (128 * QP)                  // bf16 elems per matrix
#define ATTN_SMEM ((2 + 8) * TILEB * 2)   // 184320 bytes

__global__ __launch_bounds__(256, 1)
void attention_mma(const __nv_bfloat16* __restrict__ qg_h,
                   const __nv_bfloat16* __restrict__ qg_l,
                   __nv_bfloat16* __restrict__ ohi,
                   __nv_bfloat16* __restrict__ olo) {
    extern __shared__ __nv_bfloat16 smb[];
    __nv_bfloat16* Qh = smb;
    __nv_bfloat16* Ql = Qh + TILEB;
    __nv_bfloat16* KV = Ql + TILEB;       // [buf][mat: Kh,Kl,Vh,Vl][TILEB]

    const int tid  = threadIdx.x;
    const int lane = tid & 31;
    const int wid  = tid >> 5;
    const int l16  = lane & 15;
    const int qr0  = wid * 16;

    const int bb = blockIdx.x >> 4;       // batch
    const int h  = blockIdx.x & 15;
    const int q0 = blockIdx.y * 128;

    const int qoff = h * HD_;
    const int koff = D_ + h * HD_;
    const int voff = 2 * D_ + h * HD_;

    // loader: row lr = tid>>1 (0..127), half = tid&1 selects 4 of 8 chunks
    const int lr   = tid >> 1;
    const int ch0  = (tid & 1) * 4;       // first 16B chunk index (of 8)
    const uint32_t sQh = smem_u32(Qh) + (uint32_t)(lr * QP + ch0 * 8) * 2;
    const uint32_t sQl = smem_u32(Ql) + (uint32_t)(lr * QP + ch0 * 8) * 2;
    const uint32_t sKV = smem_u32(KV) + (uint32_t)(lr * QP + ch0 * 8) * 2;

    // ---- prologue: Q + KV tile 0 ----
    {
        const size_t qrow = (size_t)(bb * S_ + q0 + lr) * (3 * D_) + qoff + ch0 * 8;
#pragma unroll
        for (int i = 0; i < 4; i++) {
            CP16(sQh + i * 16, qg_h + qrow + i * 8);
            CP16(sQl + i * 16, qg_l + qrow + i * 8);
        }
        const size_t krow = (size_t)(bb * S_ + lr) * (3 * D_);
#pragma unroll
        for (int i = 0; i < 4; i++) {
            CP16(sKV + 0 * TILEB * 2 + i * 16, qg_h + krow + koff + ch0 * 8 + i * 8);
            CP16(sKV + 1 * TILEB * 2 + i * 16, qg_l + krow + koff + ch0 * 8 + i * 8);
            CP16(sKV + 2 * TILEB * 2 + i * 16, qg_h + krow + voff + ch0 * 8 + i * 8);
            CP16(sKV + 3 * TILEB * 2 + i * 16, qg_l + krow + voff + ch0 * 8 + i * 8);
        }
        CP_COMMIT();
    }
    CP_WAIT0();
    __syncthreads();

    // ---- Q fragments (persistent) ----
    uint32_t qh[4][4], ql[4][4];
#pragma unroll
    for (int ks = 0; ks < 4; ks++) {
        uint32_t ao = (uint32_t)((qr0 + l16) * QP + ks * 16 + (lane >> 4) * 8) * 2;
        LDSM4(qh[ks][0], qh[ks][1], qh[ks][2], qh[ks][3], smem_u32(Qh) + ao);
        LDSM4(ql[ks][0], ql[ks][1], ql[ks][2], ql[ks][3], smem_u32(Ql) + ao);
    }

    float O[8][4] = {};
    float m0 = -1e30f, m1 = -1e30f, l0 = 0.f, l1 = 0.f;
    const float scale = 0.125f;

    int buf = 0;
    for (int kt = 0; kt < S_ / 128; kt++) {
        CP_WAIT0();          // KV(kt) resident
        __syncthreads();     // visible to all; all threads done with buf^1

        // issue KV(kt+1) into buf^1 (overlaps with compute below)
        if (kt + 1 < S_ / 128) {
            const size_t krow = (size_t)(bb * S_ + (kt + 1) * 128 + lr) * (3 * D_);
            const uint32_t d = sKV + (uint32_t)(buf ^ 1) * 4 * TILEB * 2;
#pragma unroll
            for (int i = 0; i < 4; i++) {
                CP16(d + 0 * TILEB * 2 + i * 16, qg_h + krow + koff + ch0 * 8 + i * 8);
                CP16(d + 1 * TILEB * 2 + i * 16, qg_l + krow + koff + ch0 * 8 + i * 8);
                CP16(d + 2 * TILEB * 2 + i * 16, qg_h + krow + voff + ch0 * 8 + i * 8);
                CP16(d + 3 * TILEB * 2 + i * 16, qg_l + krow + voff + ch0 * 8 + i * 8);
            }
            CP_COMMIT();
        }

        const __nv_bfloat16* Kh = KV + (size_t)buf * 4 * TILEB;
        const __nv_bfloat16* Kl = Kh + TILEB;
        const __nv_bfloat16* Vh = Kl + TILEB;
        const __nv_bfloat16* Vl = Vh + TILEB;
        const uint32_t kb_h = smem_u32(Kh) + (uint32_t)((l16 & 7) * QP + (l16 >> 3) * 8) * 2;
        const uint32_t kb_l = smem_u32(Kl) + (uint32_t)((l16 & 7) * QP + (l16 >> 3) * 8) * 2;
        const uint32_t vb_h = smem_u32(Vh) + (uint32_t)(l16 * QP) * 2;
        const uint32_t vb_l = smem_u32(Vl) + (uint32_t)(l16 * QP) * 2;

        // ---- S = QK^T (3-term split) ----
        float s[16][4];
#pragma unroll
        for (int nf = 0; nf < 16; nf++) {
            s[nf][0] = s[nf][1] = s[nf][2] = s[nf][3] = 0.f;
#pragma unroll
            for (int ks = 0; ks < 4; ks++) {
                const uint32_t off = (uint32_t)(nf * 8 * QP + ks * 16) * 2;
                uint32_t bh[2], bl[2];
                LDSM2(bh[0], bh[1], kb_h + off);
                LDSM2(bl[0], bl[1], kb_l + off);
                MMA_BF16(s[nf], qh[ks], bh);
                MMA_BF16(s[nf], qh[ks], bl);
                MMA_BF16(s[nf], ql[ks], bh);
            }
        }

        // ---- online softmax on fragments ----
        float mx0 = -1e30f, mx1 = -1e30f;
#pragma unroll
        for (int nf = 0; nf < 16; nf++) {
            s[nf][0] *= scale; s[nf][1] *= scale;
            s[nf][2] *= scale; s[nf][3] *= scale;
            mx0 = fmaxf(mx0, fmaxf(s[nf][0], s[nf][1]));
            mx1 = fmaxf(mx1, fmaxf(s[nf][2], s[nf][3]));
        }
        mx0 = fmaxf(mx0, __shfl_xor_sync(0xffffffffu, mx0, 1));
        mx0 = fmaxf(mx0, __shfl_xor_sync(0xffffffffu, mx0, 2));
        mx1 = fmaxf(mx1, __shfl_xor_sync(0xffffffffu, mx1, 1));
        mx1 = fmaxf(mx1, __shfl_xor_sync(0xffffffffu, mx1, 2));

        const float mn0 = fmaxf(m0, mx0);
        const float mn1 = fmaxf(m1, mx1);
        const float al0 = __expf(m0 - mn0);
        const float al1 = __expf(m1 - mn1);
        m0 = mn0; m1 = mn1;

        float rs0 = 0.f, rs1 = 0.f;
#pragma unroll
        for (int nf = 0; nf < 16; nf++) {
            s[nf][0] = __expf(s[nf][0] - m0);
            s[nf][1] = __expf(s[nf][1] - m0);
            s[nf][2] = __expf(s[nf][2] - m1);
            s[nf][3] = __expf(s[nf][3] - m1);
            rs0 += s[nf][0] + s[nf][1];
            rs1 += s[nf][2] + s[nf][3];
        }
        rs0 += __shfl_xor_sync(0xffffffffu, rs0, 1);
        rs0 += __shfl_xor_sync(0xffffffffu, rs0, 2);
        rs1 += __shfl_xor_sync(0xffffffffu, rs1, 1);
        rs1 += __shfl_xor_sync(0xffffffffu, rs1, 2);
        l0 = l0 * al0 + rs0;
        l1 = l1 * al1 + rs1;

#pragma unroll
        for (int df = 0; df < 8; df++) {
            O[df][0] *= al0; O[df][1] *= al0;
            O[df][2] *= al1; O[df][3] *= al1;
        }

        // ---- O += P @ V (3-term split; P direct from registers) ----
#pragma unroll
        for (int kk = 0; kk < 8; kk++) {
            uint32_t ah[4], alr[4];
            pack2_split(s[2 * kk][0],     s[2 * kk][1],     ah[0], alr[0]);
            pack2_split(s[2 * kk][2],     s[2 * kk][3],     ah[1], alr[1]);
            pack2_split(s[2 * kk + 1][0], s[2 * kk + 1][1], ah[2], alr[2]);
            pack2_split(s[2 * kk + 1][2], s[2 * kk + 1][3], ah[3], alr[3]);
#pragma unroll
            for (int df = 0; df < 8; df++) {
                const uint32_t off = (uint32_t)(kk * 16 * QP + df * 8) * 2;
                uint32_t vb[2], vl2[2];
                LDSM2T(vb[0],  vb[1],  vb_h + off);
                LDSM2T(vl2[0], vl2[1], vb_l + off);
                MMA_BF16(O[df], ah,  vb);
                MMA_BF16(O[df], ah,  vl2);
                MMA_BF16(O[df], alr, vb);
            }
        }
        buf ^= 1;
    }

    // ---- epilogue: normalize + split-store bf16 hi/lo ----
    const float inv0 = 1.f / l0;
    const float inv1 = 1.f / l1;
    const int qrow = q0 + qr0 + (lane >> 2);
    const int cb   = h * HD_ + (lane & 3) * 2;
#pragma unroll
    for (int df = 0; df < 8; df++) {
        uint32_t h0, lv0, h1, lv1;
        pack2_split(O[df][0] * inv0, O[df][1] * inv0, h0, lv0);
        pack2_split(O[df][2] * inv1, O[df][3] * inv1, h1, lv1);
        const size_t r0 = (size_t)(bb * S_ + qrow) * D_ + cb + df * 8;
        const size_t r1 = (size_t)(bb * S_ + qrow + 8) * D_ + cb + df * 8;
        *(uint32_t*)(ohi + r0) = h0;
        *(uint32_t*)(olo + r0) = lv0;
        *(uint32_t*)(ohi + r1) = h1;
        *(uint32_t*)(olo + r1) = lv1;
    }
}

// ---------------------------------------------------------------------------
extern "C" void kernel_launch(void* const* d_in, const int* in_sizes, int n_in,
                              void* d_out, int out_size) {
    const float* x     = (const float*)d_in[0];
    const float* Wqkv  = (const float*)d_in[1];
    const float* bqkv  = (const float*)d_in[2];
    const float* Wproj = (const float*)d_in[3];
    const float* bproj = (const float*)d_in[4];
    float* out = (float*)d_out;

    __nv_bfloat16 *qkvh, *qkvl, *ahi, *alo, *bthi, *btlo;
    cudaGetSymbolAddress((void**)&qkvh, g_qkvh);
    cudaGetSymbolAddress((void**)&qkvl, g_qkvl);
    cudaGetSymbolAddress((void**)&ahi,  g_ahi);
    cudaGetSymbolAddress((void**)&alo,  g_alo);
    cudaGetSymbolAddress((void**)&bthi, g_bthi);
    cudaGetSymbolAddress((void**)&btlo, g_btlo);

    cudaFuncSetAttribute(attention_mma,
                         cudaFuncAttributeMaxDynamicSharedMemorySize, ATTN_SMEM);
    cudaFuncSetAttribute(gemm_bf16x3<true>,
                         cudaFuncAttributeMaxDynamicSharedMemorySize, GEMM_SMEM);
    cudaFuncSetAttribute(gemm_bf16x3<false>,
                         cudaFuncAttributeMaxDynamicSharedMemorySize, GEMM_SMEM);

    const int n4 = MTOT * D_ / 4;

    // 1) prep: split x; transpose+split Wqkv -> [3072][1024]
    split_bf16<<<(n4 + 255) / 256, 256>>>(x, ahi, alo, n4);
    transpose_split_bf16<<<dim3(3 * D_ / 32, D_ / 32), dim3(32, 8)>>>(
        Wqkv, bthi, btlo, D_, 3 * D_);

    // 2) QKV projection -> bf16 hi/lo directly
    gemm_bf16x3<true><<<dim3(3 * D_ / 128, MTOT / 128), 256, GEMM_SMEM>>>(
        ahi, alo, bthi, btlo, bqkv, nullptr, qkvh, qkvl, MTOT, 3 * D_, D_);

    // 3) attention (tensor-core, pre-split inputs) -> bf16 hi/lo A operand
    attention_mma<<<dim3(B_ * H_, S_ / 128), 256, ATTN_SMEM>>>(qkvh, qkvl,
                                                               ahi, alo);

    // 4) transpose+split Wproj -> [1024][1024]
    transpose_split_bf16<<<dim3(D_ / 32, D_ / 32), dim3(32, 8)>>>(
        Wproj, bthi, btlo, D_, D_);

    // 5) output projection -> fp32 out
    gemm_bf16x3<false><<<dim3(D_ / 128, MTOT / 128), 256, GEMM_SMEM>>>(
        ahi, alo, bthi, btlo, bproj, out, nullptr, nullptr, MTOT, D_, D_);
}

// round 14
// speedup vs baseline: 2.5334x; 1.0114x over previous
#include <cuda_runtime.h>
#include <cuda_bf16.h>
#include <cstdint>
#include <math.h>

#define B_   2
#define S_   2048
#define D_   1024
#define H_   16
#define HD_  64
#define MTOT (B_ * S_)        // 4096

// Scratch (__device__ globals; no cudaMalloc allowed)
__device__ __nv_bfloat16 g_qkvh[MTOT * 3 * D_];   // qkv hi  (25 MB)
__device__ __nv_bfloat16 g_qkvl[MTOT * 3 * D_];   // qkv lo  (25 MB)
__device__ __nv_bfloat16 g_ahi[MTOT * D_];        // A-split hi (x, then att out)
__device__ __nv_bfloat16 g_alo[MTOT * D_];        // A-split lo
__device__ __nv_bfloat16 g_bthi[3 * D_ * D_];     // W^T hi [N][K]
__device__ __nv_bfloat16 g_btlo[3 * D_ * D_];     // W^T lo

// ---------------------------------------------------------------------------
// helpers
// ---------------------------------------------------------------------------
__device__ __forceinline__ uint32_t smem_u32(const void* p) {
    uint32_t a;
    asm("{ .reg .u64 t; cvta.to.shared.u64 t, %1; cvt.u32.u64 %0, t; }"
        : "=r"(a) : "l"(p));
    return a;
}

#define LDSM4(r0, r1, r2, r3, addr) \
    asm volatile("ldmatrix.sync.aligned.m8n8.x4.shared.b16 {%0,%1,%2,%3}, [%4];" \
                 : "=r"(r0), "=r"(r1), "=r"(r2), "=r"(r3) : "r"(addr))
#define LDSM2(r0, r1, addr) \
    asm volatile("ldmatrix.sync.aligned.m8n8.x2.shared.b16 {%0,%1}, [%2];" \
                 : "=r"(r0), "=r"(r1) : "r"(addr))
#define LDSM2T(r0, r1, addr) \
    asm volatile("ldmatrix.sync.aligned.m8n8.x2.trans.shared.b16 {%0,%1}, [%2];" \
                 : "=r"(r0), "=r"(r1) : "r"(addr))

#define MMA_BF16(c, a, b) \
    asm volatile("mma.sync.aligned.m16n8k16.row.col.f32.bf16.bf16.f32 " \
                 "{%0,%1,%2,%3}, {%4,%5,%6,%7}, {%8,%9}, {%0,%1,%2,%3};" \
                 : "+f"((c)[0]), "+f"((c)[1]), "+f"((c)[2]), "+f"((c)[3]) \
                 : "r"((a)[0]), "r"((a)[1]), "r"((a)[2]), "r"((a)[3]), \
                   "r"((b)[0]), "r"((b)[1]))

#define CP16(dst, src) \
    asm volatile("cp.async.cg.shared.global [%0], [%1], 16;" \
                 :: "r"(dst), "l"(src))
#define CP_COMMIT() asm volatile("cp.async.commit_group;" ::: "memory")
#define CP_WAIT0()  asm volatile("cp.async.wait_group 0;" ::: "memory")

__device__ __forceinline__ uint32_t pack_bf16(float a, float b) {
    __nv_bfloat162 t = __floats2bfloat162_rn(a, b);
    return *reinterpret_cast<uint32_t*>(&t);
}

// split a pair into hi bf16x2 + lo (residual) bf16x2
__device__ __forceinline__ void pack2_split(float a, float b,
                                            uint32_t& hi, uint32_t& lo) {
    __nv_bfloat162 h = __floats2bfloat162_rn(a, b);
    hi = *reinterpret_cast<uint32_t*>(&h);
    float ha = __bfloat162float(h.x), hb = __bfloat162float(h.y);
    __nv_bfloat162 l = __floats2bfloat162_rn(a - ha, b - hb);
    lo = *reinterpret_cast<uint32_t*>(&l);
}

// ---------------------------------------------------------------------------
// Prep: split fp32 -> bf16 hi/lo  (rowwise, [M][K] layout preserved)
// ---------------------------------------------------------------------------
__global__ void split_bf16(const float* __restrict__ src,
                           __nv_bfloat16* __restrict__ hi,
                           __nv_bfloat16* __restrict__ lo, int n4) {
    int i = blockIdx.x * blockDim.x + threadIdx.x;
    if (i >= n4) return;
    float4 v = ((const float4*)src)[i];
    float h0 = __bfloat162float(__float2bfloat16_rn(v.x));
    float h1 = __bfloat162float(__float2bfloat16_rn(v.y));
    float h2 = __bfloat162float(__float2bfloat16_rn(v.z));
    float h3 = __bfloat162float(__float2bfloat16_rn(v.w));
    uint2 ho, lw;
    ho.x = pack_bf16(h0, h1);
    ho.y = pack_bf16(h2, h3);
    lw.x = pack_bf16(v.x - h0, v.y - h1);
    lw.y = pack_bf16(v.z - h2, v.w - h3);
    ((uint2*)hi)[i] = ho;
    ((uint2*)lo)[i] = lw;
}

// Prep: W[K][N] fp32 -> W^T hi/lo bf16 [N][K]
__global__ void transpose_split_bf16(const float* __restrict__ W,
                                     __nv_bfloat16* __restrict__ Thi,
                                     __nv_bfloat16* __restrict__ Tlo,
                                     int K, int N) {
    __shared__ float t[32][33];
    int n0 = blockIdx.x * 32, k0 = blockIdx.y * 32;
    int tx = threadIdx.x, ty = threadIdx.y;   // 32 x 8
#pragma unroll
    for (int i = 0; i < 4; i++)
        t[ty + 8 * i][tx] = W[(size_t)(k0 + ty + 8 * i) * N + n0 + tx];
    __syncthreads();
#pragma unroll
    for (int i = 0; i < 4; i++) {
        float v = t[tx][ty + 8 * i];
        float h = __bfloat162float(__float2bfloat16_rn(v));
        size_t o = (size_t)(n0 + ty + 8 * i) * K + k0 + tx;
        Thi[o] = __float2bfloat16_rn(h);
        Tlo[o] = __float2bfloat16_rn(v - h);
    }
}

// ---------------------------------------------------------------------------
// Tensor-core GEMM (unchanged): C = A @ W + bias, bf16 x3 split.
// SPLIT=true: write result as bf16 hi/lo pair (Chi/Clo); else fp32 C.
// ---------------------------------------------------------------------------
#define BKP 40
#define MATB (128 * BKP * 2)
#define BUFB (4 * MATB)
#define GEMM_SMEM (2 * BUFB)

template <bool SPLIT>
__global__ __launch_bounds__(256, 1)
void gemm_bf16x3(const __nv_bfloat16* __restrict__ Ahi,
                 const __nv_bfloat16* __restrict__ Alo,
                 const __nv_bfloat16* __restrict__ Bhi,
                 const __nv_bfloat16* __restrict__ Blo,
                 const float* __restrict__ bias, float* __restrict__ C,
                 __nv_bfloat16* __restrict__ Chi,
                 __nv_bfloat16* __restrict__ Clo,
                 int M, int N, int K) {
    extern __shared__ char smraw[];
    const int tid  = threadIdx.x;
    const int lane = tid & 31;
    const int wid  = tid >> 5;
    const int m0   = blockIdx.y * 128;
    const int n0   = blockIdx.x * 128;
    const int m0w  = (wid >> 2) * 64;
    const int n0w  = (wid & 3) * 32;
    const uint32_t sb = smem_u32(smraw);

    const int lrow = tid >> 1;
    const int lk   = (tid & 1) * 16;
    const __nv_bfloat16* gAh = Ahi + (size_t)(m0 + lrow) * K + lk;
    const __nv_bfloat16* gAl = Alo + (size_t)(m0 + lrow) * K + lk;
    const __nv_bfloat16* gBh = Bhi + (size_t)(n0 + lrow) * K + lk;
    const __nv_bfloat16* gBl = Blo + (size_t)(n0 + lrow) * K + lk;
    const uint32_t sdst = (uint32_t)(lrow * (BKP * 2) + lk * 2);

    float c[4][4][4] = {};

    const int arow = lane & 15;
    const int acol = (lane >> 4) * 8;
    const int bl7  = lane & 7;
    const int bk8  = ((lane >> 3) & 1) * 8;

    {
        uint4 a0 = *(const uint4*)(gAh);     uint4 a1 = *(const uint4*)(gAh + 8);
        uint4 l0 = *(const uint4*)(gAl);     uint4 l1 = *(const uint4*)(gAl + 8);
        uint4 b0 = *(const uint4*)(gBh);     uint4 b1 = *(const uint4*)(gBh + 8);
        uint4 w0 = *(const uint4*)(gBl);     uint4 w1 = *(const uint4*)(gBl + 8);
        char* p = smraw;
        *(uint4*)(p + 0 * MATB + sdst) = a0;  *(uint4*)(p + 0 * MATB + sdst + 16) = a1;
        *(uint4*)(p + 1 * MATB + sdst) = l0;  *(uint4*)(p + 1 * MATB + sdst + 16) = l1;
        *(uint4*)(p + 2 * MATB + sdst) = b0;  *(uint4*)(p + 2 * MATB + sdst + 16) = b1;
        *(uint4*)(p + 3 * MATB + sdst) = w0;  *(uint4*)(p + 3 * MATB + sdst + 16) = w1;
    }
    __syncthreads();

    int buf = 0;
    for (int k0 = 32; k0 <= K; k0 += 32) {
        uint4 a0, a1, l0, l1, b0, b1, w0, w1;
        const bool more = (k0 < K);
        if (more) {
            a0 = *(const uint4*)(gAh + k0); a1 = *(const uint4*)(gAh + k0 + 8);
            l0 = *(const uint4*)(gAl + k0); l1 = *(const uint4*)(gAl + k0 + 8);
            b0 = *(const uint4*)(gBh + k0); b1 = *(const uint4*)(gBh + k0 + 8);
            w0 = *(const uint4*)(gBl + k0); w1 = *(const uint4*)(gBl + k0 + 8);
        }

        const uint32_t bb = sb + (uint32_t)buf * BUFB;
#pragma unroll
        for (int ks = 0; ks < 2; ks++) {
            uint32_t bh[4][2], bl[4][2];
#pragma unroll
            for (int nt = 0; nt < 4; nt++) {
                uint32_t boff = (uint32_t)((n0w + nt * 8 + bl7) * (BKP * 2)
                                           + (ks * 16 + bk8) * 2);
                LDSM2(bh[nt][0], bh[nt][1], bb + 2 * MATB + boff);
                LDSM2(bl[nt][0], bl[nt][1], bb + 3 * MATB + boff);
            }
#pragma unroll
            for (int mt = 0; mt < 4; mt++) {
                uint32_t aoff = (uint32_t)((m0w + mt * 16 + arow) * (BKP * 2)
                                           + (ks * 16 + acol) * 2);
                uint32_t ah[4], al[4];
                LDSM4(ah[0], ah[1], ah[2], ah[3], bb + 0 * MATB + aoff);
                LDSM4(al[0], al[1], al[2], al[3], bb + 1 * MATB + aoff);
#pragma unroll
                for (int nt = 0; nt < 4; nt++) {
                    MMA_BF16(c[mt][nt], ah, bh[nt]);
                    MMA_BF16(c[mt][nt], ah, bl[nt]);
                    MMA_BF16(c[mt][nt], al, bh[nt]);
                }
            }
        }

        if (more) {
            char* p = smraw + (buf ^ 1) * BUFB;
            *(uint4*)(p + 0 * MATB + sdst) = a0;  *(uint4*)(p + 0 * MATB + sdst + 16) = a1;
            *(uint4*)(p + 1 * MATB + sdst) = l0;  *(uint4*)(p + 1 * MATB + sdst + 16) = l1;
            *(uint4*)(p + 2 * MATB + sdst) = b0;  *(uint4*)(p + 2 * MATB + sdst + 16) = b1;
            *(uint4*)(p + 3 * MATB + sdst) = w0;  *(uint4*)(p + 3 * MATB + sdst + 16) = w1;
            __syncthreads();
            buf ^= 1;
        }
    }

    const int erow = lane >> 2;
    const int ecol = (lane & 3) * 2;
#pragma unroll
    for (int mt = 0; mt < 4; mt++) {
#pragma unroll
        for (int nt = 0; nt < 4; nt++) {
            const int col = n0 + n0w + nt * 8 + ecol;
            const float bi0 = bias[col], bi1 = bias[col + 1];
            const int r0 = m0 + m0w + mt * 16 + erow;
            float v00 = c[mt][nt][0] + bi0, v01 = c[mt][nt][1] + bi1;
            float v10 = c[mt][nt][2] + bi0, v11 = c[mt][nt][3] + bi1;
            if (SPLIT) {
                uint32_t h0, l0v, h1, l1v;
                pack2_split(v00, v01, h0, l0v);
                pack2_split(v10, v11, h1, l1v);
                *(uint32_t*)(Chi + (size_t)r0 * N + col) = h0;
                *(uint32_t*)(Clo + (size_t)r0 * N + col) = l0v;
                *(uint32_t*)(Chi + (size_t)(r0 + 8) * N + col) = h1;
                *(uint32_t*)(Clo + (size_t)(r0 + 8) * N + col) = l1v;
            } else {
                float2 v0, v1;
                v0.x = v00; v0.y = v01;
                v1.x = v10; v1.y = v11;
                *(float2*)(C + (size_t)r0 * N + col) = v0;
                *(float2*)(C + (size_t)(r0 + 8) * N + col) = v1;
            }
        }
    }
}

// ---------------------------------------------------------------------------
// Tensor-core flash attention v3: split-K warps.
// 512 threads (16 warps, 1 CTA/SM). Warp (qg = wid>>1, kh = wid&1) owns
// q rows qg*16..+15 and k cols kh*64..+63 of every 128-k tile.
// Two online-softmax states per q-group are combined at the end via smem.
// smem: Qh,Ql + 2 x (Kh,Kl,Vh,Vl), each [128][72] bf16 = 184320 B.
// ---------------------------------------------------------------------------
#define QP 72
#define TILEB (128 * QP)                  // bf16 elems per matrix
#define ATTN_SMEM ((2 + 8) * TILEB * 2)   // 184320 bytes

__global__ __launch_bounds__(512, 1)
void attention_mma(const __nv_bfloat16* __restrict__ qg_h,
                   const __nv_bfloat16* __restrict__ qg_l,
                   __nv_bfloat16* __restrict__ ohi,
                   __nv_bfloat16* __restrict__ olo) {
    extern __shared__ __nv_bfloat16 smb[];
    __nv_bfloat16* Qh = smb;
    __nv_bfloat16* Ql = Qh + TILEB;
    __nv_bfloat16* KV = Ql + TILEB;       // [buf][mat: Kh,Kl,Vh,Vl][TILEB]

    const int tid  = threadIdx.x;
    const int lane = tid & 31;
    const int wid  = tid >> 5;
    const int l16  = lane & 15;
    const int qg   = wid >> 1;            // q group 0..7
    const int kh   = wid & 1;             // k half 0..1
    const int qr0  = qg * 16;

    const int bb = blockIdx.x >> 4;       // batch
    const int h  = blockIdx.x & 15;
    const int q0 = blockIdx.y * 128;

    const int qoff = h * HD_;
    const int koff = D_ + h * HD_;
    const int voff = 2 * D_ + h * HD_;

    // loader: 512 threads, row lr = tid>>2 (0..127), chunks ch0,ch0+1 of 8
    const int lr   = tid >> 2;
    const int ch0  = (tid & 3) * 2;       // 16B-chunk index: 0,2,4,6
    const uint32_t sQh = smem_u32(Qh) + (uint32_t)(lr * QP + ch0 * 8) * 2;
    const uint32_t sQl = smem_u32(Ql) + (uint32_t)(lr * QP + ch0 * 8) * 2;
    const uint32_t sKV = smem_u32(KV) + (uint32_t)(lr * QP + ch0 * 8) * 2;

    // ---- prologue: Q + KV tile 0 ----
    {
        const size_t qrow = (size_t)(bb * S_ + q0 + lr) * (3 * D_) + qoff + ch0 * 8;
#pragma unroll
        for (int i = 0; i < 2; i++) {
            CP16(sQh + i * 16, qg_h + qrow + i * 8);
            CP16(sQl + i * 16, qg_l + qrow + i * 8);
        }
        const size_t krow = (size_t)(bb * S_ + lr) * (3 * D_);
#pragma unroll
        for (int i = 0; i < 2; i++) {
            CP16(sKV + 0 * TILEB * 2 + i * 16, qg_h + krow + koff + ch0 * 8 + i * 8);
            CP16(sKV + 1 * TILEB * 2 + i * 16, qg_l + krow + koff + ch0 * 8 + i * 8);
            CP16(sKV + 2 * TILEB * 2 + i * 16, qg_h + krow + voff + ch0 * 8 + i * 8);
            CP16(sKV + 3 * TILEB * 2 + i * 16, qg_l + krow + voff + ch0 * 8 + i * 8);
        }
        CP_COMMIT();
    }
    CP_WAIT0();
    __syncthreads();

    // ---- Q fragments (persistent) ----
    uint32_t qh[4][4], ql[4][4];
#pragma unroll
    for (int ks = 0; ks < 4; ks++) {
        uint32_t ao = (uint32_t)((qr0 + l16) * QP + ks * 16 + (lane >> 4) * 8) * 2;
        LDSM4(qh[ks][0], qh[ks][1], qh[ks][2], qh[ks][3], smem_u32(Qh) + ao);
        LDSM4(ql[ks][0], ql[ks][1], ql[ks][2], ql[ks][3], smem_u32(Ql) + ao);
    }

    float O[8][4] = {};
    float m0 = -1e30f, m1 = -1e30f, l0 = 0.f, l1 = 0.f;
    const float scale = 0.125f;

    int buf = 0;
    for (int kt = 0; kt < S_ / 128; kt++) {
        CP_WAIT0();          // KV(kt) resident
        __syncthreads();     // visible to all; all threads done with buf^1

        // issue KV(kt+1) into buf^1 (overlaps with compute below)
        if (kt + 1 < S_ / 128) {
            const size_t krow = (size_t)(bb * S_ + (kt + 1) * 128 + lr) * (3 * D_);
            const uint32_t d = sKV + (uint32_t)(buf ^ 1) * 4 * TILEB * 2;
#pragma unroll
            for (int i = 0; i < 2; i++) {
                CP16(d + 0 * TILEB * 2 + i * 16, qg_h + krow + koff + ch0 * 8 + i * 8);
                CP16(d + 1 * TILEB * 2 + i * 16, qg_l + krow + koff + ch0 * 8 + i * 8);
                CP16(d + 2 * TILEB * 2 + i * 16, qg_h + krow + voff + ch0 * 8 + i * 8);
                CP16(d + 3 * TILEB * 2 + i * 16, qg_l + krow + voff + ch0 * 8 + i * 8);
            }
            CP_COMMIT();
        }

        const __nv_bfloat16* Kh = KV + (size_t)buf * 4 * TILEB;
        const __nv_bfloat16* Kl = Kh + TILEB;
        const __nv_bfloat16* Vh = Kl + TILEB;
        const __nv_bfloat16* Vl = Vh + TILEB;
        // warp's k-half: rows kh*64 .. +63 of the K/V tiles
        const uint32_t kb_h = smem_u32(Kh)
            + (uint32_t)((kh * 64 + (l16 & 7)) * QP + (l16 >> 3) * 8) * 2;
        const uint32_t kb_l = smem_u32(Kl)
            + (uint32_t)((kh * 64 + (l16 & 7)) * QP + (l16 >> 3) * 8) * 2;
        const uint32_t vb_h = smem_u32(Vh) + (uint32_t)((kh * 64 + l16) * QP) * 2;
        const uint32_t vb_l = smem_u32(Vl) + (uint32_t)((kh * 64 + l16) * QP) * 2;

        // ---- S = QK^T over 64 cols (3-term split) ----
        float s[8][4];
#pragma unroll
        for (int nf = 0; nf < 8; nf++) {
            s[nf][0] = s[nf][1] = s[nf][2] = s[nf][3] = 0.f;
#pragma unroll
            for (int ks = 0; ks < 4; ks++) {
                const uint32_t off = (uint32_t)(nf * 8 * QP + ks * 16) * 2;
                uint32_t bh[2], bl[2];
                LDSM2(bh[0], bh[1], kb_h + off);
                LDSM2(bl[0], bl[1], kb_l + off);
                MMA_BF16(s[nf], qh[ks], bh);
                MMA_BF16(s[nf], qh[ks], bl);
                MMA_BF16(s[nf], ql[ks], bh);
            }
        }

        // ---- online softmax on fragments (rows spread over 4 lanes) ----
        float mx0 = -1e30f, mx1 = -1e30f;
#pragma unroll
        for (int nf = 0; nf < 8; nf++) {
            s[nf][0] *= scale; s[nf][1] *= scale;
            s[nf][2] *= scale; s[nf][3] *= scale;
            mx0 = fmaxf(mx0, fmaxf(s[nf][0], s[nf][1]));
            mx1 = fmaxf(mx1, fmaxf(s[nf][2], s[nf][3]));
        }
        mx0 = fmaxf(mx0, __shfl_xor_sync(0xffffffffu, mx0, 1));
        mx0 = fmaxf(mx0, __shfl_xor_sync(0xffffffffu, mx0, 2));
        mx1 = fmaxf(mx1, __shfl_xor_sync(0xffffffffu, mx1, 1));
        mx1 = fmaxf(mx1, __shfl_xor_sync(0xffffffffu, mx1, 2));

        const float mn0 = fmaxf(m0, mx0);
        const float mn1 = fmaxf(m1, mx1);
        const float al0 = __expf(m0 - mn0);
        const float al1 = __expf(m1 - mn1);
        m0 = mn0; m1 = mn1;

        float rs0 = 0.f, rs1 = 0.f;
#pragma unroll
        for (int nf = 0; nf < 8; nf++) {
            s[nf][0] = __expf(s[nf][0] - m0);
            s[nf][1] = __expf(s[nf][1] - m0);
            s[nf][2] = __expf(s[nf][2] - m1);
            s[nf][3] = __expf(s[nf][3] - m1);
            rs0 += s[nf][0] + s[nf][1];
            rs1 += s[nf][2] + s[nf][3];
        }
        rs0 += __shfl_xor_sync(0xffffffffu, rs0, 1);
        rs0 += __shfl_xor_sync(0xffffffffu, rs0, 2);
        rs1 += __shfl_xor_sync(0xffffffffu, rs1, 1);
        rs1 += __shfl_xor_sync(0xffffffffu, rs1, 2);
        l0 = l0 * al0 + rs0;
        l1 = l1 * al1 + rs1;

#pragma unroll
        for (int df = 0; df < 8; df++) {
            O[df][0] *= al0; O[df][1] *= al0;
            O[df][2] *= al1; O[df][3] *= al1;
        }

        // ---- O += P @ V over this warp's 64 k-rows ----
#pragma unroll
        for (int kk = 0; kk < 4; kk++) {
            uint32_t ah[4], alr[4];
            pack2_split(s[2 * kk][0],     s[2 * kk][1],     ah[0], alr[0]);
            pack2_split(s[2 * kk][2],     s[2 * kk][3],     ah[1], alr[1]);
            pack2_split(s[2 * kk + 1][0], s[2 * kk + 1][1], ah[2], alr[2]);
            pack2_split(s[2 * kk + 1][2], s[2 * kk + 1][3], ah[3], alr[3]);
#pragma unroll
            for (int df = 0; df < 8; df++) {
                const uint32_t off = (uint32_t)(kk * 16 * QP + df * 8) * 2;
                uint32_t vb[2], vl2[2];
                LDSM2T(vb[0],  vb[1],  vb_h + off);
                LDSM2T(vl2[0], vl2[1], vb_l + off);
                MMA_BF16(O[df], ah,  vb);
                MMA_BF16(O[df], ah,  vl2);
                MMA_BF16(O[df], alr, vb);
            }
        }
        buf ^= 1;
    }

    // ---- combine the two k-half states per q-group (via reused KV smem) ----
    __syncthreads();                       // all compute done; smem reusable
    float* mlb = (float*)smb;              // [8 g][2 kh][16 row][2 (m,l)]
    float* Ost = (float*)smb + 1024;       // [8 g][16 row][64 col]

    const int r = lane >> 2;
    if ((lane & 3) == 0) {
        float* p = mlb + ((qg * 2 + kh) * 16 + r) * 2;
        p[0] = m0;  p[1] = l0;
        float* p8 = mlb + ((qg * 2 + kh) * 16 + r + 8) * 2;
        p8[0] = m1; p8[1] = l1;
    }
    __syncthreads();

    const float* pa0 = mlb + ((qg * 2 + 0) * 16 + r) * 2;
    const float* pb0 = mlb + ((qg * 2 + 1) * 16 + r) * 2;
    const float* pa1 = mlb + ((qg * 2 + 0) * 16 + r + 8) * 2;
    const float* pb1 = mlb + ((qg * 2 + 1) * 16 + r + 8) * 2;
    const float ma0 = pa0[0], la0 = pa0[1], mb0 = pb0[0], lb0 = pb0[1];
    const float ma1 = pa1[0], la1 = pa1[1], mb1 = pb1[0], lb1 = pb1[1];
    const float mm0 = fmaxf(ma0, mb0), mm1 = fmaxf(ma1, mb1);
    const float fa0 = __expf(ma0 - mm0), fb0 = __expf(mb0 - mm0);
    const float fa1 = __expf(ma1 - mm1), fb1 = __expf(mb1 - mm1);
    const float lc0 = la0 * fa0 + lb0 * fb0;
    const float lc1 = la1 * fa1 + lb1 * fb1;

    const int ccol = (lane & 3) * 2;
    if (kh == 1) {                         // stage scaled O of half 1
#pragma unroll
        for (int df = 0; df < 8; df++) {
            float* p0 = Ost + (qg * 16 + r) * 64 + df * 8 + ccol;
            float* p1 = Ost + (qg * 16 + r + 8) * 64 + df * 8 + ccol;
            p0[0] = O[df][0] * fb0;  p0[1] = O[df][1] * fb0;
            p1[0] = O[df][2] * fb1;  p1[1] = O[df][3] * fb1;
        }
    }
    __syncthreads();

    if (kh == 0) {                         // merge + normalize + split-store
        const float inv0 = 1.f / lc0;
        const float inv1 = 1.f / lc1;
        const int qrow = q0 + qr0 + r;
        const int cb   = h * HD_ + ccol;
#pragma unroll
        for (int df = 0; df < 8; df++) {
            const float* p0 = Ost + (qg * 16 + r) * 64 + df * 8 + ccol;
            const float* p1 = Ost + (qg * 16 + r + 8) * 64 + df * 8 + ccol;
            float v00 = (O[df][0] * fa0 + p0[0]) * inv0;
            float v01 = (O[df][1] * fa0 + p0[1]) * inv0;
            float v10 = (O[df][2] * fa1 + p1[0]) * inv1;
            float v11 = (O[df][3] * fa1 + p1[1]) * inv1;
            uint32_t h0, lv0, h1, lv1;
            pack2_split(v00, v01, h0, lv0);
            pack2_split(v10, v11, h1, lv1);
            const size_t r0 = (size_t)(bb * S_ + qrow) * D_ + cb + df * 8;
            const size_t r1 = (size_t)(bb * S_ + qrow + 8) * D_ + cb + df * 8;
            *(uint32_t*)(ohi + r0) = h0;
            *(uint32_t*)(olo + r0) = lv0;
            *(uint32_t*)(ohi + r1) = h1;
            *(uint32_t*)(olo + r1) = lv1;
        }
    }
}

// ---------------------------------------------------------------------------
extern "C" void kernel_launch(void* const* d_in, const int* in_sizes, int n_in,
                              void* d_out, int out_size) {
    const float* x     = (const float*)d_in[0];
    const float* Wqkv  = (const float*)d_in[1];
    const float* bqkv  = (const float*)d_in[2];
    const float* Wproj = (const float*)d_in[3];
    const float* bproj = (const float*)d_in[4];
    float* out = (float*)d_out;

    __nv_bfloat16 *qkvh, *qkvl, *ahi, *alo, *bthi, *btlo;
    cudaGetSymbolAddress((void**)&qkvh, g_qkvh);
    cudaGetSymbolAddress((void**)&qkvl, g_qkvl);
    cudaGetSymbolAddress((void**)&ahi,  g_ahi);
    cudaGetSymbolAddress((void**)&alo,  g_alo);
    cudaGetSymbolAddress((void**)&bthi, g_bthi);
    cudaGetSymbolAddress((void**)&btlo, g_btlo);

    cudaFuncSetAttribute(attention_mma,
                         cudaFuncAttributeMaxDynamicSharedMemorySize, ATTN_SMEM);
    cudaFuncSetAttribute(gemm_bf16x3<true>,
                         cudaFuncAttributeMaxDynamicSharedMemorySize, GEMM_SMEM);
    cudaFuncSetAttribute(gemm_bf16x3<false>,
                         cudaFuncAttributeMaxDynamicSharedMemorySize, GEMM_SMEM);

    const int n4 = MTOT * D_ / 4;

    // 1) prep: split x; transpose+split Wqkv -> [3072][1024]
    split_bf16<<<(n4 + 255) / 256, 256>>>(x, ahi, alo, n4);
    transpose_split_bf16<<<dim3(3 * D_ / 32, D_ / 32), dim3(32, 8)>>>(
        Wqkv, bthi, btlo, D_, 3 * D_);

    // 2) QKV projection -> bf16 hi/lo directly
    gemm_bf16x3<true><<<dim3(3 * D_ / 128, MTOT / 128), 256, GEMM_SMEM>>>(
        ahi, alo, bthi, btlo, bqkv, nullptr, qkvh, qkvl, MTOT, 3 * D_, D_);

    // 3) attention (split-K tensor-core) -> bf16 hi/lo A operand
    attention_mma<<<dim3(B_ * H_, S_ / 128), 512, ATTN_SMEM>>>(qkvh, qkvl,
                                                               ahi, alo);

    // 4) transpose+split Wproj -> [1024][1024]
    transpose_split_bf16<<<dim3(D_ / 32, D_ / 32), dim3(32, 8)>>>(
        Wproj, bthi, btlo, D_, D_);

    // 5) output projection -> fp32 out
    gemm_bf16x3<false><<<dim3(D_ / 128, MTOT / 128), 256, GEMM_SMEM>>>(
        ahi, alo, bthi, btlo, bproj, out, nullptr, nullptr, MTOT, D_, D_);
}